// round 1
// baseline (speedup 1.0000x reference)
#include <cuda_runtime.h>

#define B_SZ   8
#define SEQ    1024
#define CH     768
#define NHEAD  12
#define HDIM   64
#define QKV_LD (3*CH)      /* 2304 */
#define ATT_SCALE 0.125f   /* 64^-0.5 */

#define PS_PAD 132
#define VS_PAD 68

// Scratch (device globals; no runtime allocation allowed)
__device__ float g_qkv[(size_t)B_SZ * SEQ * QKV_LD];  // [B*N, 3*C]
__device__ float g_att[(size_t)B_SZ * SEQ * CH];      // [B*N, C] attention output

// ---------------------------------------------------------------------------
// Tiled fp32 SGEMM: C[M,N] = A[M,K] @ B[K,N] (+ bias). 128x128 tile, BK=16,
// 256 threads, 8x8 register tile per thread.
// ---------------------------------------------------------------------------
__global__ __launch_bounds__(256, 2) void sgemm_bias_kernel(
    const float* __restrict__ A, const float* __restrict__ Bm,
    const float* __restrict__ bias, float* __restrict__ Cm,
    int M, int Nn, int K, int has_bias)
{
    __shared__ float As[16][128];   // transposed: As[k][m]
    __shared__ float Bs[16][128];   // Bs[k][n]

    const int tid = threadIdx.x;
    const int bm = blockIdx.y * 128;
    const int bn = blockIdx.x * 128;
    const int tx = tid & 15;        // n direction
    const int ty = tid >> 4;        // m direction

    const int a_row = tid >> 1;         // 0..127
    const int a_k   = (tid & 1) * 8;    // 0 or 8
    const int b_kr  = tid >> 4;         // 0..15
    const int b_col = (tid & 15) * 8;   // 0..120

    const float* Ap = A + (size_t)(bm + a_row) * K + a_k;
    const float* Bp = Bm + (size_t)b_kr * Nn + bn + b_col;

    float acc[8][8];
#pragma unroll
    for (int i = 0; i < 8; i++)
#pragma unroll
        for (int jj = 0; jj < 8; jj++) acc[i][jj] = 0.f;

    for (int k0 = 0; k0 < K; k0 += 16) {
        float4 av0 = *(const float4*)(Ap + k0);
        float4 av1 = *(const float4*)(Ap + k0 + 4);
        float4 bv0 = *(const float4*)(Bp + (size_t)k0 * Nn);
        float4 bv1 = *(const float4*)(Bp + (size_t)k0 * Nn + 4);

        As[a_k + 0][a_row] = av0.x;
        As[a_k + 1][a_row] = av0.y;
        As[a_k + 2][a_row] = av0.z;
        As[a_k + 3][a_row] = av0.w;
        As[a_k + 4][a_row] = av1.x;
        As[a_k + 5][a_row] = av1.y;
        As[a_k + 6][a_row] = av1.z;
        As[a_k + 7][a_row] = av1.w;
        *(float4*)&Bs[b_kr][b_col]     = bv0;
        *(float4*)&Bs[b_kr][b_col + 4] = bv1;
        __syncthreads();

#pragma unroll
        for (int kk = 0; kk < 16; kk++) {
            float a[8], b[8];
            *(float4*)&a[0] = *(const float4*)&As[kk][ty * 8];
            *(float4*)&a[4] = *(const float4*)&As[kk][ty * 8 + 4];
            *(float4*)&b[0] = *(const float4*)&Bs[kk][tx * 8];
            *(float4*)&b[4] = *(const float4*)&Bs[kk][tx * 8 + 4];
#pragma unroll
            for (int i = 0; i < 8; i++)
#pragma unroll
                for (int jj = 0; jj < 8; jj++)
                    acc[i][jj] = fmaf(a[i], b[jj], acc[i][jj]);
        }
        __syncthreads();
    }

    float bj[8];
#pragma unroll
    for (int jj = 0; jj < 8; jj++) bj[jj] = 0.f;
    if (has_bias) {
        *(float4*)&bj[0] = *(const float4*)(bias + bn + tx * 8);
        *(float4*)&bj[4] = *(const float4*)(bias + bn + tx * 8 + 4);
    }

#pragma unroll
    for (int i = 0; i < 8; i++) {
        const size_t row = (size_t)(bm + ty * 8 + i);
        float* Cp = Cm + row * Nn + bn + tx * 8;
        float4 o0 = make_float4(acc[i][0] + bj[0], acc[i][1] + bj[1],
                                acc[i][2] + bj[2], acc[i][3] + bj[3]);
        float4 o1 = make_float4(acc[i][4] + bj[4], acc[i][5] + bj[5],
                                acc[i][6] + bj[6], acc[i][7] + bj[7]);
        *(float4*)Cp       = o0;
        *(float4*)(Cp + 4) = o1;
    }
}

// ---------------------------------------------------------------------------
// Flash attention, fp32. Grid: (SEQ/128 q-tiles, B*H). 256 threads.
// Per block: Q tile [128,64] resident; loop over 8 KV tiles of 128 rows.
// S = Q@K^T via 8x8 register tiles; online softmax with 16-lane shuffle
// reductions; P staged to SMEM [m][n]; O += P@V with 8x4 per-thread tile.
// ---------------------------------------------------------------------------
__global__ __launch_bounds__(256, 1) void flash_attn_kernel()
{
    extern __shared__ float smf[];
    float* Qs = smf;                       // [64][128]  (d-major)
    float* Ks = smf + 64 * 128;            // [64][128]  (d-major)
    float* Vs = smf + 2 * 64 * 128;        // [128][VS_PAD]
    float* Ps = Vs + 128 * VS_PAD;         // [128][PS_PAD]

    const int tid = threadIdx.x;
    const int tx = tid & 15;
    const int ty = tid >> 4;
    const int q0 = blockIdx.x * 128;
    const int b  = blockIdx.y / NHEAD;
    const int h  = blockIdx.y % NHEAD;

    const float* qbase = g_qkv + (size_t)b * SEQ * QKV_LD + h * HDIM;
    const float* kbase = qbase + CH;
    const float* vbase = qbase + 2 * CH;

    // Load + scale Q tile (transposed to Qs[d][m]), once per block.
    {
        const int m  = tid >> 1;
        const int d0 = (tid & 1) * 32;
        const float* src = qbase + (size_t)(q0 + m) * QKV_LD + d0;
#pragma unroll
        for (int i = 0; i < 32; i += 4) {
            float4 v = *(const float4*)(src + i);
            Qs[(d0 + i + 0) * 128 + m] = v.x * ATT_SCALE;
            Qs[(d0 + i + 1) * 128 + m] = v.y * ATT_SCALE;
            Qs[(d0 + i + 2) * 128 + m] = v.z * ATT_SCALE;
            Qs[(d0 + i + 3) * 128 + m] = v.w * ATT_SCALE;
        }
    }

    float mstate[8], lstate[8], Oacc[8][4];
#pragma unroll
    for (int r = 0; r < 8; r++) {
        mstate[r] = -1e30f;
        lstate[r] = 0.f;
#pragma unroll
        for (int c = 0; c < 4; c++) Oacc[r][c] = 0.f;
    }

    for (int j = 0; j < SEQ; j += 128) {
        __syncthreads();   // previous PV done before overwriting K/V
        {
            const int n  = tid >> 1;
            const int d0 = (tid & 1) * 32;
            const float* ksrc = kbase + (size_t)(j + n) * QKV_LD + d0;
            const float* vsrc = vbase + (size_t)(j + n) * QKV_LD + d0;
#pragma unroll
            for (int i = 0; i < 32; i += 4) {
                float4 kv = *(const float4*)(ksrc + i);
                Ks[(d0 + i + 0) * 128 + n] = kv.x;
                Ks[(d0 + i + 1) * 128 + n] = kv.y;
                Ks[(d0 + i + 2) * 128 + n] = kv.z;
                Ks[(d0 + i + 3) * 128 + n] = kv.w;
                float4 vv = *(const float4*)(vsrc + i);
                *(float4*)&Vs[n * VS_PAD + d0 + i] = vv;
            }
        }
        __syncthreads();

        // S = Q @ K^T  (128x128, k-dim 64)
        float s[8][8];
#pragma unroll
        for (int r = 0; r < 8; r++)
#pragma unroll
            for (int c = 0; c < 8; c++) s[r][c] = 0.f;

#pragma unroll 8
        for (int kk = 0; kk < 64; kk++) {
            float a[8], bb[8];
            *(float4*)&a[0]  = *(const float4*)&Qs[kk * 128 + ty * 8];
            *(float4*)&a[4]  = *(const float4*)&Qs[kk * 128 + ty * 8 + 4];
            *(float4*)&bb[0] = *(const float4*)&Ks[kk * 128 + tx * 8];
            *(float4*)&bb[4] = *(const float4*)&Ks[kk * 128 + tx * 8 + 4];
#pragma unroll
            for (int r = 0; r < 8; r++)
#pragma unroll
                for (int c = 0; c < 8; c++)
                    s[r][c] = fmaf(a[r], bb[c], s[r][c]);
        }

        // Online softmax. Row groups = 16 threads (same ty) within one warp
        // half; xor-shuffle reductions with offsets < 16 stay in-group.
#pragma unroll
        for (int r = 0; r < 8; r++) {
            float mx = s[r][0];
#pragma unroll
            for (int c = 1; c < 8; c++) mx = fmaxf(mx, s[r][c]);
#pragma unroll
            for (int off = 1; off < 16; off <<= 1)
                mx = fmaxf(mx, __shfl_xor_sync(0xffffffffu, mx, off));
            const float mnew = fmaxf(mstate[r], mx);
            const float corr = __expf(mstate[r] - mnew);
            float ps = 0.f;
#pragma unroll
            for (int c = 0; c < 8; c++) {
                const float p = __expf(s[r][c] - mnew);
                s[r][c] = p;
                ps += p;
            }
#pragma unroll
            for (int off = 1; off < 16; off <<= 1)
                ps += __shfl_xor_sync(0xffffffffu, ps, off);
            lstate[r] = lstate[r] * corr + ps;
            mstate[r] = mnew;
#pragma unroll
            for (int c = 0; c < 4; c++) Oacc[r][c] *= corr;

            *(float4*)&Ps[(ty * 8 + r) * PS_PAD + tx * 8] =
                make_float4(s[r][0], s[r][1], s[r][2], s[r][3]);
            *(float4*)&Ps[(ty * 8 + r) * PS_PAD + tx * 8 + 4] =
                make_float4(s[r][4], s[r][5], s[r][6], s[r][7]);
        }
        __syncthreads();

        // O += P @ V   (per-thread tile: 8 rows x 4 d-cols)
#pragma unroll 4
        for (int nn = 0; nn < 128; nn++) {
            const float4 vv = *(const float4*)&Vs[nn * VS_PAD + tx * 4];
#pragma unroll
            for (int r = 0; r < 8; r++) {
                const float p = Ps[(ty * 8 + r) * PS_PAD + nn];
                Oacc[r][0] = fmaf(p, vv.x, Oacc[r][0]);
                Oacc[r][1] = fmaf(p, vv.y, Oacc[r][1]);
                Oacc[r][2] = fmaf(p, vv.z, Oacc[r][2]);
                Oacc[r][3] = fmaf(p, vv.w, Oacc[r][3]);
            }
        }
    }

    // Normalize and write [B*N, C] with C = h*64 + d
#pragma unroll
    for (int r = 0; r < 8; r++) {
        const float inv = 1.f / lstate[r];
        const size_t row = (size_t)b * SEQ + q0 + ty * 8 + r;
        float4 o = make_float4(Oacc[r][0] * inv, Oacc[r][1] * inv,
                               Oacc[r][2] * inv, Oacc[r][3] * inv);
        *(float4*)&g_att[row * CH + h * HDIM + tx * 4] = o;
    }
}

// ---------------------------------------------------------------------------
extern "C" void kernel_launch(void* const* d_in, const int* in_sizes, int n_in,
                              void* d_out, int out_size)
{
    const float* x      = (const float*)d_in[0];
    const float* w_qkv  = (const float*)d_in[1];
    const float* w_proj = (const float*)d_in[2];
    const float* b_proj = (const float*)d_in[3];
    float* out = (float*)d_out;

    float* qkv = nullptr;
    float* att = nullptr;
    cudaGetSymbolAddress((void**)&qkv, g_qkv);
    cudaGetSymbolAddress((void**)&att, g_att);

    // 1) QKV projection: [8192,768] @ [768,2304]
    sgemm_bias_kernel<<<dim3(QKV_LD / 128, (B_SZ * SEQ) / 128), 256>>>(
        x, w_qkv, nullptr, qkv, B_SZ * SEQ, QKV_LD, CH, 0);

    // 2) Flash attention
    const size_t smem =
        (size_t)(2 * 64 * 128 + 128 * VS_PAD + 128 * PS_PAD) * sizeof(float);
    cudaFuncSetAttribute(flash_attn_kernel,
                         cudaFuncAttributeMaxDynamicSharedMemorySize,
                         (int)smem);
    flash_attn_kernel<<<dim3(SEQ / 128, B_SZ * NHEAD), 256, smem>>>();

    // 3) Output projection + bias: [8192,768] @ [768,768]
    sgemm_bias_kernel<<<dim3(CH / 128, (B_SZ * SEQ) / 128), 256>>>(
        att, w_proj, b_proj, out, B_SZ * SEQ, CH, CH, 1);
}

// round 3
// speedup vs baseline: 1.2433x; 1.2433x over previous
#include <cuda_runtime.h>
#include <cuda_bf16.h>
#include <cstdint>

#define B_SZ   8
#define SEQ    1024
#define CH     768
#define NHEAD  12
#define HDIM   64
#define QKV_LD (3*CH)      /* 2304 */
#define ATT_SCALE 0.125f   /* 64^-0.5 */

#define PS_PAD 132
#define VS_PAD 68

// ---------------------------------------------------------------------------
// Scratch (device globals; runtime allocation is forbidden)
// ---------------------------------------------------------------------------
__device__ float g_qkv[(size_t)B_SZ * SEQ * QKV_LD];  // [B*N, 3*C]
__device__ float g_att[(size_t)B_SZ * SEQ * CH];      // [B*N, C]
__device__ __nv_bfloat16 g_wqh[(size_t)QKV_LD * CH];  // w_qkv^T hi  [N, K]
__device__ __nv_bfloat16 g_wql[(size_t)QKV_LD * CH];  // w_qkv^T lo
__device__ __nv_bfloat16 g_wph[(size_t)CH * CH];      // w_proj^T hi [N, K]
__device__ __nv_bfloat16 g_wpl[(size_t)CH * CH];      // w_proj^T lo

// ---------------------------------------------------------------------------
__device__ __forceinline__ uint32_t smem_u32(const void* p) {
    uint32_t a;
    asm("{ .reg .u64 t; cvta.to.shared.u64 t, %1; cvt.u32.u64 %0, t; }"
        : "=r"(a) : "l"(p));
    return a;
}
__device__ __forceinline__ void ldmatrix_x4(uint32_t* r, uint32_t addr) {
    asm volatile("ldmatrix.sync.aligned.m8n8.x4.shared.b16 {%0,%1,%2,%3}, [%4];"
                 : "=r"(r[0]), "=r"(r[1]), "=r"(r[2]), "=r"(r[3]) : "r"(addr));
}
__device__ __forceinline__ void mma_bf16(float* d, const uint32_t* a,
                                         const uint32_t* b) {
    asm volatile(
        "mma.sync.aligned.m16n8k16.row.col.f32.bf16.bf16.f32 "
        "{%0,%1,%2,%3},{%4,%5,%6,%7},{%8,%9},{%0,%1,%2,%3};"
        : "+f"(d[0]), "+f"(d[1]), "+f"(d[2]), "+f"(d[3])
        : "r"(a[0]), "r"(a[1]), "r"(a[2]), "r"(a[3]), "r"(b[0]), "r"(b[1]));
}
__device__ __forceinline__ uint32_t pack_bf2(__nv_bfloat16 a, __nv_bfloat16 b) {
    return (uint32_t)__bfloat16_as_ushort(a) |
           ((uint32_t)__bfloat16_as_ushort(b) << 16);
}

// ---------------------------------------------------------------------------
// Weight prep: W[K,N] fp32 -> WT_hi/WT_lo [N,K] bf16 (transpose + split)
// ---------------------------------------------------------------------------
__global__ void transpose_split_kernel(const float* __restrict__ W,
                                       __nv_bfloat16* __restrict__ Th,
                                       __nv_bfloat16* __restrict__ Tl,
                                       int K, int Nn)
{
    __shared__ float tile[32][33];
    const int n0 = blockIdx.x * 32;
    const int k0 = blockIdx.y * 32;
    const int tx = threadIdx.x;
    for (int i = threadIdx.y; i < 32; i += 8)
        tile[i][tx] = W[(size_t)(k0 + i) * Nn + n0 + tx];
    __syncthreads();
    for (int i = threadIdx.y; i < 32; i += 8) {
        const float v = tile[tx][i];            // = W[k0+tx][n0+i]
        const __nv_bfloat16 h = __float2bfloat16(v);
        const __nv_bfloat16 l = __float2bfloat16(v - __bfloat162float(h));
        const size_t o = (size_t)(n0 + i) * K + k0 + tx;
        Th[o] = h;
        Tl[o] = l;
    }
}

// ---------------------------------------------------------------------------
// bf16-split GEMM via mma.sync: C[M,N] = A[M,K] @ BT[N,K]^T (+bias)
// CTA tile 128x128, BK=32, 8 warps (4m x 2n), warp tile 32x64.
// Single smem buffer + register prefetch. smem rows padded to 40 bf16 (80B).
// ---------------------------------------------------------------------------
#define LDA 40   /* bf16 units per smem row (32 data + 8 pad) */

__global__ __launch_bounds__(256) void gemm_mma_kernel(
    const float* __restrict__ A,
    const __nv_bfloat16* __restrict__ Bh, const __nv_bfloat16* __restrict__ Bl,
    const float* __restrict__ bias, float* __restrict__ C,
    int M, int Nn, int K, int has_bias)
{
    __shared__ __align__(16) __nv_bfloat16 sAh[128 * LDA];
    __shared__ __align__(16) __nv_bfloat16 sAl[128 * LDA];
    __shared__ __align__(16) __nv_bfloat16 sBh[128 * LDA];
    __shared__ __align__(16) __nv_bfloat16 sBl[128 * LDA];

    const int tid  = threadIdx.x;
    const int wid  = tid >> 5;
    const int lane = tid & 31;
    const int wr   = wid >> 1;       // warp m index (0..3)
    const int wc   = wid & 1;        // warp n index (0..1)
    const int bm   = blockIdx.y * 128;
    const int bn   = blockIdx.x * 128;

    // loader mapping: each thread owns row r, 16-col half
    const int r    = tid >> 1;
    const int half = tid & 1;
    const float* ap = A + (size_t)(bm + r) * K + half * 16;
    const __nv_bfloat16* bhp = Bh + (size_t)(bn + r) * K + half * 16;
    const __nv_bfloat16* blp = Bl + (size_t)(bn + r) * K + half * 16;
    const uint32_t st_off = (uint32_t)(r * LDA + half * 16);

    // ldmatrix addressing (per kk computed inside)
    const int lrow = lane & 15;
    const int lcol = (lane >> 4) << 3;   // 0 or 8 (bf16 units)
    const uint32_t uAh = smem_u32(sAh), uAl = smem_u32(sAl);
    const uint32_t uBh = smem_u32(sBh), uBl = smem_u32(sBl);

    float acc[2][8][4];
#pragma unroll
    for (int a = 0; a < 2; a++)
#pragma unroll
        for (int b = 0; b < 8; b++)
#pragma unroll
            for (int j = 0; j < 4; j++) acc[a][b][j] = 0.f;

    float4 va[4];
    uint4  vbh[2], vbl[2];

    // prologue: load iter 0
#pragma unroll
    for (int j = 0; j < 4; j++) va[j] = *(const float4*)(ap + j * 4);
    vbh[0] = *(const uint4*)(bhp);     vbh[1] = *(const uint4*)(bhp + 8);
    vbl[0] = *(const uint4*)(blp);     vbl[1] = *(const uint4*)(blp + 8);

    const int NIT = K / 32;
    for (int it = 0; it < NIT; it++) {
        // store prefetched regs -> smem (convert/split A)
        {
            uint4 qh[2], ql[2];
#pragma unroll
            for (int q = 0; q < 2; q++) {
                uint32_t ph[2], pl[2];
#pragma unroll
                for (int p = 0; p < 2; p++) {
                    const float4 v = va[q * 2 + p];
                    const __nv_bfloat16 h0 = __float2bfloat16(v.x);
                    const __nv_bfloat16 h1 = __float2bfloat16(v.y);
                    const __nv_bfloat16 h2 = __float2bfloat16(v.z);
                    const __nv_bfloat16 h3 = __float2bfloat16(v.w);
                    ph[0] = pack_bf2(h0, h1);
                    ph[1] = pack_bf2(h2, h3);
                    pl[0] = pack_bf2(
                        __float2bfloat16(v.x - __bfloat162float(h0)),
                        __float2bfloat16(v.y - __bfloat162float(h1)));
                    pl[1] = pack_bf2(
                        __float2bfloat16(v.z - __bfloat162float(h2)),
                        __float2bfloat16(v.w - __bfloat162float(h3)));
                    if (p == 0) {
                        qh[q].x = ph[0]; qh[q].y = ph[1];
                        ql[q].x = pl[0]; ql[q].y = pl[1];
                    } else {
                        qh[q].z = ph[0]; qh[q].w = ph[1];
                        ql[q].z = pl[0]; ql[q].w = pl[1];
                    }
                }
            }
            *(uint4*)&sAh[st_off]     = qh[0];
            *(uint4*)&sAh[st_off + 8] = qh[1];
            *(uint4*)&sAl[st_off]     = ql[0];
            *(uint4*)&sAl[st_off + 8] = ql[1];
            *(uint4*)&sBh[st_off]     = vbh[0];
            *(uint4*)&sBh[st_off + 8] = vbh[1];
            *(uint4*)&sBl[st_off]     = vbl[0];
            *(uint4*)&sBl[st_off + 8] = vbl[1];
        }
        __syncthreads();

        // issue next iter's global loads early (hidden behind MMA work)
        if (it + 1 < NIT) {
            const int k0 = (it + 1) * 32;
#pragma unroll
            for (int j = 0; j < 4; j++)
                va[j] = *(const float4*)(ap + k0 + j * 4);
            vbh[0] = *(const uint4*)(bhp + k0);
            vbh[1] = *(const uint4*)(bhp + k0 + 8);
            vbl[0] = *(const uint4*)(blp + k0);
            vbl[1] = *(const uint4*)(blp + k0 + 8);
        }

        // compute: 2 k-steps of 16
#pragma unroll
        for (int kk = 0; kk < 2; kk++) {
            const uint32_t cByte = (uint32_t)((kk * 16 + lcol) * 2);
            uint32_t ah[2][4], al[2][4];
#pragma unroll
            for (int a = 0; a < 2; a++) {
                const uint32_t ro =
                    (uint32_t)((wr * 32 + a * 16 + lrow) * (LDA * 2)) + cByte;
                ldmatrix_x4(ah[a], uAh + ro);
                ldmatrix_x4(al[a], uAl + ro);
            }
            uint32_t bh[8][2], bl[8][2];
#pragma unroll
            for (int g = 0; g < 4; g++) {
                uint32_t t[4];
                const uint32_t ro =
                    (uint32_t)((wc * 64 + g * 16 + lrow) * (LDA * 2)) + cByte;
                ldmatrix_x4(t, uBh + ro);
                bh[g * 2][0] = t[0]; bh[g * 2][1] = t[2];
                bh[g * 2 + 1][0] = t[1]; bh[g * 2 + 1][1] = t[3];
                ldmatrix_x4(t, uBl + ro);
                bl[g * 2][0] = t[0]; bl[g * 2][1] = t[2];
                bl[g * 2 + 1][0] = t[1]; bl[g * 2 + 1][1] = t[3];
            }
#pragma unroll
            for (int a = 0; a < 2; a++)
#pragma unroll
                for (int b = 0; b < 8; b++) {
                    mma_bf16(acc[a][b], ah[a], bh[b]);
                    mma_bf16(acc[a][b], ah[a], bl[b]);
                    mma_bf16(acc[a][b], al[a], bh[b]);
                }
        }
        __syncthreads();
    }

    // epilogue: fragment-native stores (+bias)
    const int g  = lane >> 2;
    const int t2 = (lane & 3) * 2;
#pragma unroll
    for (int a = 0; a < 2; a++) {
        const int row0 = bm + wr * 32 + a * 16 + g;
#pragma unroll
        for (int b = 0; b < 8; b++) {
            const int col = bn + wc * 64 + b * 8 + t2;
            float bx = 0.f, by = 0.f;
            if (has_bias) {
                bx = bias[col];
                by = bias[col + 1];
            }
            float2 o0 = make_float2(acc[a][b][0] + bx, acc[a][b][1] + by);
            float2 o1 = make_float2(acc[a][b][2] + bx, acc[a][b][3] + by);
            *(float2*)(C + (size_t)row0 * Nn + col) = o0;
            *(float2*)(C + (size_t)(row0 + 8) * Nn + col) = o1;
        }
    }
}

// ---------------------------------------------------------------------------
// Flash attention, fp32 (unchanged)
// ---------------------------------------------------------------------------
__global__ __launch_bounds__(256, 1) void flash_attn_kernel()
{
    extern __shared__ float smf[];
    float* Qs = smf;
    float* Ks = smf + 64 * 128;
    float* Vs = smf + 2 * 64 * 128;
    float* Ps = Vs + 128 * VS_PAD;

    const int tid = threadIdx.x;
    const int tx = tid & 15;
    const int ty = tid >> 4;
    const int q0 = blockIdx.x * 128;
    const int b  = blockIdx.y / NHEAD;
    const int h  = blockIdx.y % NHEAD;

    const float* qbase = g_qkv + (size_t)b * SEQ * QKV_LD + h * HDIM;
    const float* kbase = qbase + CH;
    const float* vbase = qbase + 2 * CH;

    {
        const int m  = tid >> 1;
        const int d0 = (tid & 1) * 32;
        const float* src = qbase + (size_t)(q0 + m) * QKV_LD + d0;
#pragma unroll
        for (int i = 0; i < 32; i += 4) {
            float4 v = *(const float4*)(src + i);
            Qs[(d0 + i + 0) * 128 + m] = v.x * ATT_SCALE;
            Qs[(d0 + i + 1) * 128 + m] = v.y * ATT_SCALE;
            Qs[(d0 + i + 2) * 128 + m] = v.z * ATT_SCALE;
            Qs[(d0 + i + 3) * 128 + m] = v.w * ATT_SCALE;
        }
    }

    float mstate[8], lstate[8], Oacc[8][4];
#pragma unroll
    for (int rr = 0; rr < 8; rr++) {
        mstate[rr] = -1e30f;
        lstate[rr] = 0.f;
#pragma unroll
        for (int cc = 0; cc < 4; cc++) Oacc[rr][cc] = 0.f;
    }

    for (int j = 0; j < SEQ; j += 128) {
        __syncthreads();
        {
            const int n  = tid >> 1;
            const int d0 = (tid & 1) * 32;
            const float* ksrc = kbase + (size_t)(j + n) * QKV_LD + d0;
            const float* vsrc = vbase + (size_t)(j + n) * QKV_LD + d0;
#pragma unroll
            for (int i = 0; i < 32; i += 4) {
                float4 kv = *(const float4*)(ksrc + i);
                Ks[(d0 + i + 0) * 128 + n] = kv.x;
                Ks[(d0 + i + 1) * 128 + n] = kv.y;
                Ks[(d0 + i + 2) * 128 + n] = kv.z;
                Ks[(d0 + i + 3) * 128 + n] = kv.w;
                float4 vv = *(const float4*)(vsrc + i);
                *(float4*)&Vs[n * VS_PAD + d0 + i] = vv;
            }
        }
        __syncthreads();

        float s[8][8];
#pragma unroll
        for (int rr = 0; rr < 8; rr++)
#pragma unroll
            for (int cc = 0; cc < 8; cc++) s[rr][cc] = 0.f;

#pragma unroll 8
        for (int kk = 0; kk < 64; kk++) {
            float a[8], bb[8];
            *(float4*)&a[0]  = *(const float4*)&Qs[kk * 128 + ty * 8];
            *(float4*)&a[4]  = *(const float4*)&Qs[kk * 128 + ty * 8 + 4];
            *(float4*)&bb[0] = *(const float4*)&Ks[kk * 128 + tx * 8];
            *(float4*)&bb[4] = *(const float4*)&Ks[kk * 128 + tx * 8 + 4];
#pragma unroll
            for (int rr = 0; rr < 8; rr++)
#pragma unroll
                for (int cc = 0; cc < 8; cc++)
                    s[rr][cc] = fmaf(a[rr], bb[cc], s[rr][cc]);
        }

#pragma unroll
        for (int rr = 0; rr < 8; rr++) {
            float mx = s[rr][0];
#pragma unroll
            for (int cc = 1; cc < 8; cc++) mx = fmaxf(mx, s[rr][cc]);
#pragma unroll
            for (int off = 1; off < 16; off <<= 1)
                mx = fmaxf(mx, __shfl_xor_sync(0xffffffffu, mx, off));
            const float mnew = fmaxf(mstate[rr], mx);
            const float corr = __expf(mstate[rr] - mnew);
            float ps = 0.f;
#pragma unroll
            for (int cc = 0; cc < 8; cc++) {
                const float p = __expf(s[rr][cc] - mnew);
                s[rr][cc] = p;
                ps += p;
            }
#pragma unroll
            for (int off = 1; off < 16; off <<= 1)
                ps += __shfl_xor_sync(0xffffffffu, ps, off);
            lstate[rr] = lstate[rr] * corr + ps;
            mstate[rr] = mnew;
#pragma unroll
            for (int cc = 0; cc < 4; cc++) Oacc[rr][cc] *= corr;

            *(float4*)&Ps[(ty * 8 + rr) * PS_PAD + tx * 8] =
                make_float4(s[rr][0], s[rr][1], s[rr][2], s[rr][3]);
            *(float4*)&Ps[(ty * 8 + rr) * PS_PAD + tx * 8 + 4] =
                make_float4(s[rr][4], s[rr][5], s[rr][6], s[rr][7]);
        }
        __syncthreads();

#pragma unroll 4
        for (int nn = 0; nn < 128; nn++) {
            const float4 vv = *(const float4*)&Vs[nn * VS_PAD + tx * 4];
#pragma unroll
            for (int rr = 0; rr < 8; rr++) {
                const float p = Ps[(ty * 8 + rr) * PS_PAD + nn];
                Oacc[rr][0] = fmaf(p, vv.x, Oacc[rr][0]);
                Oacc[rr][1] = fmaf(p, vv.y, Oacc[rr][1]);
                Oacc[rr][2] = fmaf(p, vv.z, Oacc[rr][2]);
                Oacc[rr][3] = fmaf(p, vv.w, Oacc[rr][3]);
            }
        }
    }

#pragma unroll
    for (int rr = 0; rr < 8; rr++) {
        const float inv = 1.f / lstate[rr];
        const size_t row = (size_t)b * SEQ + q0 + ty * 8 + rr;
        float4 o = make_float4(Oacc[rr][0] * inv, Oacc[rr][1] * inv,
                               Oacc[rr][2] * inv, Oacc[rr][3] * inv);
        *(float4*)&g_att[row * CH + h * HDIM + tx * 4] = o;
    }
}

// ---------------------------------------------------------------------------
extern "C" void kernel_launch(void* const* d_in, const int* in_sizes, int n_in,
                              void* d_out, int out_size)
{
    const float* x      = (const float*)d_in[0];
    const float* w_qkv  = (const float*)d_in[1];
    const float* w_proj = (const float*)d_in[2];
    const float* b_proj = (const float*)d_in[3];
    float* out = (float*)d_out;

    float *qkv, *att;
    __nv_bfloat16 *wqh, *wql, *wph, *wpl;
    cudaGetSymbolAddress((void**)&qkv, g_qkv);
    cudaGetSymbolAddress((void**)&att, g_att);
    cudaGetSymbolAddress((void**)&wqh, g_wqh);
    cudaGetSymbolAddress((void**)&wql, g_wql);
    cudaGetSymbolAddress((void**)&wph, g_wph);
    cudaGetSymbolAddress((void**)&wpl, g_wpl);

    // 0) Weight transpose + bf16 split
    transpose_split_kernel<<<dim3(QKV_LD / 32, CH / 32), dim3(32, 8)>>>(
        w_qkv, wqh, wql, CH, QKV_LD);
    transpose_split_kernel<<<dim3(CH / 32, CH / 32), dim3(32, 8)>>>(
        w_proj, wph, wpl, CH, CH);

    // 1) QKV projection: [8192,768] @ [768,2304] via bf16-split mma.sync
    gemm_mma_kernel<<<dim3(QKV_LD / 128, (B_SZ * SEQ) / 128), 256>>>(
        x, wqh, wql, nullptr, qkv, B_SZ * SEQ, QKV_LD, CH, 0);

    // 2) Flash attention (fp32)
    const size_t fsmem =
        (size_t)(2 * 64 * 128 + 128 * VS_PAD + 128 * PS_PAD) * sizeof(float);
    cudaFuncSetAttribute(flash_attn_kernel,
                         cudaFuncAttributeMaxDynamicSharedMemorySize, (int)fsmem);
    flash_attn_kernel<<<dim3(SEQ / 128, B_SZ * NHEAD), 256, fsmem>>>();

    // 3) Output projection + bias via bf16-split mma.sync
    gemm_mma_kernel<<<dim3(CH / 128, (B_SZ * SEQ) / 128), 256>>>(
        att, wph, wpl, b_proj, out, B_SZ * SEQ, CH, CH, 1);
}

// round 5
// speedup vs baseline: 1.7700x; 1.4236x over previous
#include <cuda_runtime.h>
#include <cuda_bf16.h>
#include <cstdint>

#define B_SZ   8
#define SEQ    1024
#define CH     768
#define NHEAD  12
#define HDIM   64
#define QKV_LD (3*CH)      /* 2304 */
#define ATT_SCALE 0.125f   /* 64^-0.5 */

// ---------------------------------------------------------------------------
// Scratch (device globals; runtime allocation is forbidden)
// ---------------------------------------------------------------------------
__device__ __nv_bfloat16 g_qh[(size_t)B_SZ * SEQ * QKV_LD];  // qkv hi (q pre-scaled)
__device__ __nv_bfloat16 g_ql[(size_t)B_SZ * SEQ * QKV_LD];  // qkv lo
__device__ float g_att[(size_t)B_SZ * SEQ * CH];             // attention out fp32
__device__ __nv_bfloat16 g_wqh[(size_t)QKV_LD * CH];
__device__ __nv_bfloat16 g_wql[(size_t)QKV_LD * CH];
__device__ __nv_bfloat16 g_wph[(size_t)CH * CH];
__device__ __nv_bfloat16 g_wpl[(size_t)CH * CH];

// ---------------------------------------------------------------------------
__device__ __forceinline__ uint32_t smem_u32(const void* p) {
    uint32_t a;
    asm("{ .reg .u64 t; cvta.to.shared.u64 t, %1; cvt.u32.u64 %0, t; }"
        : "=r"(a) : "l"(p));
    return a;
}
__device__ __forceinline__ void ldmatrix_x4(uint32_t* r, uint32_t addr) {
    asm volatile("ldmatrix.sync.aligned.m8n8.x4.shared.b16 {%0,%1,%2,%3}, [%4];"
                 : "=r"(r[0]), "=r"(r[1]), "=r"(r[2]), "=r"(r[3]) : "r"(addr));
}
__device__ __forceinline__ void mma_bf16(float* d, const uint32_t* a,
                                         const uint32_t* b) {
    asm volatile(
        "mma.sync.aligned.m16n8k16.row.col.f32.bf16.bf16.f32 "
        "{%0,%1,%2,%3},{%4,%5,%6,%7},{%8,%9},{%0,%1,%2,%3};"
        : "+f"(d[0]), "+f"(d[1]), "+f"(d[2]), "+f"(d[3])
        : "r"(a[0]), "r"(a[1]), "r"(a[2]), "r"(a[3]), "r"(b[0]), "r"(b[1]));
}
__device__ __forceinline__ uint32_t pack_bf2(__nv_bfloat16 a, __nv_bfloat16 b) {
    return (uint32_t)__bfloat16_as_ushort(a) |
           ((uint32_t)__bfloat16_as_ushort(b) << 16);
}
__device__ __forceinline__ void split_pack(float x, float y,
                                           uint32_t& hi, uint32_t& lo) {
    const __nv_bfloat16 hx = __float2bfloat16(x);
    const __nv_bfloat16 hy = __float2bfloat16(y);
    hi = pack_bf2(hx, hy);
    lo = pack_bf2(__float2bfloat16(x - __bfloat162float(hx)),
                  __float2bfloat16(y - __bfloat162float(hy)));
}

// ---------------------------------------------------------------------------
// Weight prep: W[K,N] fp32 -> WT hi/lo [N,K] bf16
// ---------------------------------------------------------------------------
__global__ void transpose_split_kernel(const float* __restrict__ W,
                                       __nv_bfloat16* __restrict__ Th,
                                       __nv_bfloat16* __restrict__ Tl,
                                       int K, int Nn)
{
    __shared__ float tile[32][33];
    const int n0 = blockIdx.x * 32;
    const int k0 = blockIdx.y * 32;
    const int tx = threadIdx.x;
    for (int i = threadIdx.y; i < 32; i += 8)
        tile[i][tx] = W[(size_t)(k0 + i) * Nn + n0 + tx];
    __syncthreads();
    for (int i = threadIdx.y; i < 32; i += 8) {
        const float v = tile[tx][i];
        const __nv_bfloat16 h = __float2bfloat16(v);
        const __nv_bfloat16 l = __float2bfloat16(v - __bfloat162float(h));
        const size_t o = (size_t)(n0 + i) * K + k0 + tx;
        Th[o] = h;
        Tl[o] = l;
    }
}

// ---------------------------------------------------------------------------
// bf16-split GEMM via mma.sync. Two epilogue modes:
//  Chi!=null : write bf16 hi/lo split (cols < qcols pre-scaled by ATT_SCALE)
//  else      : write fp32 + bias
// ---------------------------------------------------------------------------
#define LDA 40

__global__ __launch_bounds__(256) void gemm_mma_kernel(
    const float* __restrict__ A,
    const __nv_bfloat16* __restrict__ Bh, const __nv_bfloat16* __restrict__ Bl,
    const float* __restrict__ bias, float* __restrict__ C,
    __nv_bfloat16* __restrict__ Chi, __nv_bfloat16* __restrict__ Clo,
    int M, int Nn, int K, int has_bias, int qcols)
{
    __shared__ __align__(16) __nv_bfloat16 sAh[128 * LDA];
    __shared__ __align__(16) __nv_bfloat16 sAl[128 * LDA];
    __shared__ __align__(16) __nv_bfloat16 sBh[128 * LDA];
    __shared__ __align__(16) __nv_bfloat16 sBl[128 * LDA];

    const int tid  = threadIdx.x;
    const int wid  = tid >> 5;
    const int lane = tid & 31;
    const int wr   = wid >> 1;
    const int wc   = wid & 1;
    const int bm   = blockIdx.y * 128;
    const int bn   = blockIdx.x * 128;

    const int r    = tid >> 1;
    const int half = tid & 1;
    const float* ap = A + (size_t)(bm + r) * K + half * 16;
    const __nv_bfloat16* bhp = Bh + (size_t)(bn + r) * K + half * 16;
    const __nv_bfloat16* blp = Bl + (size_t)(bn + r) * K + half * 16;
    const uint32_t st_off = (uint32_t)(r * LDA + half * 16);

    const int lrow = lane & 15;
    const int lcol = (lane >> 4) << 3;
    const uint32_t uAh = smem_u32(sAh), uAl = smem_u32(sAl);
    const uint32_t uBh = smem_u32(sBh), uBl = smem_u32(sBl);

    float acc[2][8][4];
#pragma unroll
    for (int a = 0; a < 2; a++)
#pragma unroll
        for (int b = 0; b < 8; b++)
#pragma unroll
            for (int j = 0; j < 4; j++) acc[a][b][j] = 0.f;

    float4 va[4];
    uint4  vbh[2], vbl[2];
#pragma unroll
    for (int j = 0; j < 4; j++) va[j] = *(const float4*)(ap + j * 4);
    vbh[0] = *(const uint4*)(bhp);     vbh[1] = *(const uint4*)(bhp + 8);
    vbl[0] = *(const uint4*)(blp);     vbl[1] = *(const uint4*)(blp + 8);

    const int NIT = K / 32;
    for (int it = 0; it < NIT; it++) {
        {
            uint4 qh[2], ql[2];
#pragma unroll
            for (int q = 0; q < 2; q++) {
                uint32_t h0, h1, l0, l1;
                split_pack(va[q * 2].x, va[q * 2].y, h0, l0);
                split_pack(va[q * 2].z, va[q * 2].w, h1, l1);
                qh[q].x = h0; qh[q].y = h1; ql[q].x = l0; ql[q].y = l1;
                split_pack(va[q * 2 + 1].x, va[q * 2 + 1].y, h0, l0);
                split_pack(va[q * 2 + 1].z, va[q * 2 + 1].w, h1, l1);
                qh[q].z = h0; qh[q].w = h1; ql[q].z = l0; ql[q].w = l1;
            }
            *(uint4*)&sAh[st_off]     = qh[0];
            *(uint4*)&sAh[st_off + 8] = qh[1];
            *(uint4*)&sAl[st_off]     = ql[0];
            *(uint4*)&sAl[st_off + 8] = ql[1];
            *(uint4*)&sBh[st_off]     = vbh[0];
            *(uint4*)&sBh[st_off + 8] = vbh[1];
            *(uint4*)&sBl[st_off]     = vbl[0];
            *(uint4*)&sBl[st_off + 8] = vbl[1];
        }
        __syncthreads();

        if (it + 1 < NIT) {
            const int k0 = (it + 1) * 32;
#pragma unroll
            for (int j = 0; j < 4; j++)
                va[j] = *(const float4*)(ap + k0 + j * 4);
            vbh[0] = *(const uint4*)(bhp + k0);
            vbh[1] = *(const uint4*)(bhp + k0 + 8);
            vbl[0] = *(const uint4*)(blp + k0);
            vbl[1] = *(const uint4*)(blp + k0 + 8);
        }

#pragma unroll
        for (int kk = 0; kk < 2; kk++) {
            const uint32_t cByte = (uint32_t)((kk * 16 + lcol) * 2);
            uint32_t ah[2][4], al[2][4];
#pragma unroll
            for (int a = 0; a < 2; a++) {
                const uint32_t ro =
                    (uint32_t)((wr * 32 + a * 16 + lrow) * (LDA * 2)) + cByte;
                ldmatrix_x4(ah[a], uAh + ro);
                ldmatrix_x4(al[a], uAl + ro);
            }
            uint32_t bh[8][2], bl[8][2];
#pragma unroll
            for (int g = 0; g < 4; g++) {
                uint32_t t[4];
                const uint32_t ro =
                    (uint32_t)((wc * 64 + g * 16 + lrow) * (LDA * 2)) + cByte;
                ldmatrix_x4(t, uBh + ro);
                bh[g * 2][0] = t[0]; bh[g * 2][1] = t[2];
                bh[g * 2 + 1][0] = t[1]; bh[g * 2 + 1][1] = t[3];
                ldmatrix_x4(t, uBl + ro);
                bl[g * 2][0] = t[0]; bl[g * 2][1] = t[2];
                bl[g * 2 + 1][0] = t[1]; bl[g * 2 + 1][1] = t[3];
            }
#pragma unroll
            for (int a = 0; a < 2; a++)
#pragma unroll
                for (int b = 0; b < 8; b++) {
                    mma_bf16(acc[a][b], ah[a], bh[b]);
                    mma_bf16(acc[a][b], ah[a], bl[b]);
                    mma_bf16(acc[a][b], al[a], bh[b]);
                }
        }
        __syncthreads();
    }

    const int g  = lane >> 2;
    const int t2 = (lane & 3) * 2;
#pragma unroll
    for (int a = 0; a < 2; a++) {
        const int row0 = bm + wr * 32 + a * 16 + g;
#pragma unroll
        for (int b = 0; b < 8; b++) {
            const int col = bn + wc * 64 + b * 8 + t2;
            if (Chi) {
                const float sc = (col < qcols) ? ATT_SCALE : 1.f;
                uint32_t h0, l0, h1, l1;
                split_pack(acc[a][b][0] * sc, acc[a][b][1] * sc, h0, l0);
                split_pack(acc[a][b][2] * sc, acc[a][b][3] * sc, h1, l1);
                const size_t o0 = (size_t)row0 * Nn + col;
                const size_t o1 = (size_t)(row0 + 8) * Nn + col;
                *(uint32_t*)(Chi + o0) = h0;
                *(uint32_t*)(Clo + o0) = l0;
                *(uint32_t*)(Chi + o1) = h1;
                *(uint32_t*)(Clo + o1) = l1;
            } else {
                float bx = 0.f, by = 0.f;
                if (has_bias) { bx = bias[col]; by = bias[col + 1]; }
                *(float2*)(C + (size_t)row0 * Nn + col) =
                    make_float2(acc[a][b][0] + bx, acc[a][b][1] + by);
                *(float2*)(C + (size_t)(row0 + 8) * Nn + col) =
                    make_float2(acc[a][b][2] + bx, acc[a][b][3] + by);
            }
        }
    }
}

// ---------------------------------------------------------------------------
// Flash attention via bf16-split mma.sync.
// Grid (SEQ/128, B*H), 256 threads (8 warps x 16 q-rows).
// ---------------------------------------------------------------------------
#define KLD 72    /* bf16 per K/Q smem row (64 data + 8 pad)   */
#define VLD 136   /* bf16 per Vt smem row (128 data + 8 pad)   */
#define OKH 0
#define OKL (128 * KLD)
#define OVH (2 * 128 * KLD)
#define OVL (2 * 128 * KLD + 64 * VLD)
#define FLASH_SMEM ((2 * 128 * KLD + 2 * 64 * VLD) * 2)

__global__ __launch_bounds__(256, 1) void flash_mma_kernel()
{
    extern __shared__ __align__(16) __nv_bfloat16 sm[];
    __nv_bfloat16* Kh = sm + OKH;
    __nv_bfloat16* Kl = sm + OKL;
    __nv_bfloat16* Vh = sm + OVH;
    __nv_bfloat16* Vl = sm + OVL;

    const int tid  = threadIdx.x;
    const int wid  = tid >> 5;
    const int lane = tid & 31;
    const int lrow = lane & 15;
    const int lcol = (lane >> 4) << 3;
    const int q0 = blockIdx.x * 128;
    const int b  = blockIdx.y / NHEAD;
    const int h  = blockIdx.y % NHEAD;

    const size_t tokbase = (size_t)b * SEQ;
    const __nv_bfloat16* qh_g = g_qh + tokbase * QKV_LD + h * HDIM;
    const __nv_bfloat16* ql_g = g_ql + tokbase * QKV_LD + h * HDIM;
    const __nv_bfloat16* kh_g = qh_g + CH;
    const __nv_bfloat16* kl_g = ql_g + CH;
    const __nv_bfloat16* vh_g = qh_g + 2 * CH;
    const __nv_bfloat16* vl_g = ql_g + 2 * CH;

    const uint32_t uKh = smem_u32(Kh), uKl = smem_u32(Kl);
    const uint32_t uVh = smem_u32(Vh), uVl = smem_u32(Vl);

    // loader mapping: row = tid>>1, 32-elem half = (tid&1)*32
    const int ldr  = tid >> 1;
    const int ldh  = (tid & 1) * 32;

    // ---- stage Q into K buffers (32 bf16 = 4x uint4 per thread) ----
    {
        const __nv_bfloat16* sh = qh_g + (size_t)(q0 + ldr) * QKV_LD + ldh;
        const __nv_bfloat16* sl = ql_g + (size_t)(q0 + ldr) * QKV_LD + ldh;
#pragma unroll
        for (int i = 0; i < 4; i++) {
            *(uint4*)&Kh[ldr * KLD + ldh + i * 8] = *(const uint4*)(sh + i * 8);
            *(uint4*)&Kl[ldr * KLD + ldh + i * 8] = *(const uint4*)(sl + i * 8);
        }
    }
    __syncthreads();

    uint32_t qfh[4][4], qfl[4][4];
#pragma unroll
    for (int ks = 0; ks < 4; ks++) {
        const uint32_t ro =
            (uint32_t)((wid * 16 + lrow) * (KLD * 2)) + (ks * 16 + lcol) * 2;
        ldmatrix_x4(qfh[ks], uKh + ro);
        ldmatrix_x4(qfl[ks], uKl + ro);
    }

    float m0 = -1e30f, m1 = -1e30f, l0 = 0.f, l1 = 0.f;
    float oacc[8][4];
#pragma unroll
    for (int j = 0; j < 8; j++)
#pragma unroll
        for (int c = 0; c < 4; c++) oacc[j][c] = 0.f;

    for (int jt = 0; jt < SEQ; jt += 128) {
        __syncthreads();   // protect K/V buffers (incl. Q staging on iter 0)
        // ---- stage K ([key][d]) and V transposed ([d][key]) ----
        {
            const __nv_bfloat16* skh = kh_g + (size_t)(jt + ldr) * QKV_LD + ldh;
            const __nv_bfloat16* skl = kl_g + (size_t)(jt + ldr) * QKV_LD + ldh;
#pragma unroll
            for (int i = 0; i < 4; i++) {
                *(uint4*)&Kh[ldr * KLD + ldh + i * 8] = *(const uint4*)(skh + i * 8);
                *(uint4*)&Kl[ldr * KLD + ldh + i * 8] = *(const uint4*)(skl + i * 8);
            }
            const __nv_bfloat16* svh = vh_g + (size_t)(jt + ldr) * QKV_LD + ldh;
            const __nv_bfloat16* svl = vl_g + (size_t)(jt + ldr) * QKV_LD + ldh;
            uint4 th[4], tl[4];
#pragma unroll
            for (int i = 0; i < 4; i++) {
                th[i] = *(const uint4*)(svh + i * 8);
                tl[i] = *(const uint4*)(svl + i * 8);
            }
            const ushort* ph = (const ushort*)th;
            const ushort* pl = (const ushort*)tl;
#pragma unroll
            for (int i = 0; i < 32; i++) {
                ((ushort*)Vh)[(ldh + i) * VLD + ldr] = ph[i];
                ((ushort*)Vl)[(ldh + i) * VLD + ldr] = pl[i];
            }
        }
        __syncthreads();

        // ---- S = Q @ K^T (3-term) ----
        float sacc[16][4];
#pragma unroll
        for (int j = 0; j < 16; j++)
#pragma unroll
            for (int c = 0; c < 4; c++) sacc[j][c] = 0.f;

#pragma unroll
        for (int ks = 0; ks < 4; ks++) {
            const uint32_t cByte = (uint32_t)((ks * 16 + lcol) * 2);
#pragma unroll
            for (int ng = 0; ng < 4; ng++) {
                uint32_t bh[4][2], bl[4][2], t[4];
#pragma unroll
                for (int h2 = 0; h2 < 2; h2++) {
                    const uint32_t ro =
                        (uint32_t)((ng * 32 + h2 * 16 + lrow) * (KLD * 2)) + cByte;
                    ldmatrix_x4(t, uKh + ro);
                    bh[h2 * 2][0] = t[0]; bh[h2 * 2][1] = t[2];
                    bh[h2 * 2 + 1][0] = t[1]; bh[h2 * 2 + 1][1] = t[3];
                    ldmatrix_x4(t, uKl + ro);
                    bl[h2 * 2][0] = t[0]; bl[h2 * 2][1] = t[2];
                    bl[h2 * 2 + 1][0] = t[1]; bl[h2 * 2 + 1][1] = t[3];
                }
#pragma unroll
                for (int f = 0; f < 4; f++) {
                    float* d = sacc[ng * 4 + f];
                    mma_bf16(d, qfh[ks], bh[f]);
                    mma_bf16(d, qfh[ks], bl[f]);
                    mma_bf16(d, qfl[ks], bh[f]);
                }
            }
        }

        // ---- online softmax (rows g and g+8; 4-lane shuffle groups) ----
        float mx0 = sacc[0][0], mx1 = sacc[0][2];
#pragma unroll
        for (int j = 0; j < 16; j++) {
            mx0 = fmaxf(mx0, fmaxf(sacc[j][0], sacc[j][1]));
            mx1 = fmaxf(mx1, fmaxf(sacc[j][2], sacc[j][3]));
        }
        mx0 = fmaxf(mx0, __shfl_xor_sync(0xffffffffu, mx0, 1));
        mx0 = fmaxf(mx0, __shfl_xor_sync(0xffffffffu, mx0, 2));
        mx1 = fmaxf(mx1, __shfl_xor_sync(0xffffffffu, mx1, 1));
        mx1 = fmaxf(mx1, __shfl_xor_sync(0xffffffffu, mx1, 2));

        const float mn0 = fmaxf(m0, mx0);
        const float mn1 = fmaxf(m1, mx1);
        const float cr0 = __expf(m0 - mn0);
        const float cr1 = __expf(m1 - mn1);
        m0 = mn0; m1 = mn1;

        float ps0 = 0.f, ps1 = 0.f;
#pragma unroll
        for (int j = 0; j < 16; j++) {
            sacc[j][0] = __expf(sacc[j][0] - mn0);
            sacc[j][1] = __expf(sacc[j][1] - mn0);
            sacc[j][2] = __expf(sacc[j][2] - mn1);
            sacc[j][3] = __expf(sacc[j][3] - mn1);
            ps0 += sacc[j][0] + sacc[j][1];
            ps1 += sacc[j][2] + sacc[j][3];
        }
        ps0 += __shfl_xor_sync(0xffffffffu, ps0, 1);
        ps0 += __shfl_xor_sync(0xffffffffu, ps0, 2);
        ps1 += __shfl_xor_sync(0xffffffffu, ps1, 1);
        ps1 += __shfl_xor_sync(0xffffffffu, ps1, 2);
        l0 = l0 * cr0 + ps0;
        l1 = l1 * cr1 + ps1;

#pragma unroll
        for (int j = 0; j < 8; j++) {
            oacc[j][0] *= cr0; oacc[j][1] *= cr0;
            oacc[j][2] *= cr1; oacc[j][3] *= cr1;
        }

        // ---- O += P @ V (3-term; P packed from sacc in-register) ----
#pragma unroll
        for (int ks = 0; ks < 8; ks++) {
            uint32_t pah[4], pal[4];
            split_pack(sacc[2 * ks][0], sacc[2 * ks][1], pah[0], pal[0]);
            split_pack(sacc[2 * ks][2], sacc[2 * ks][3], pah[1], pal[1]);
            split_pack(sacc[2 * ks + 1][0], sacc[2 * ks + 1][1], pah[2], pal[2]);
            split_pack(sacc[2 * ks + 1][2], sacc[2 * ks + 1][3], pah[3], pal[3]);

            const uint32_t cByte = (uint32_t)((ks * 16 + lcol) * 2);
#pragma unroll
            for (int nd = 0; nd < 4; nd++) {
                uint32_t vbh[2][2], vbl[2][2], t[4];
                const uint32_t ro =
                    (uint32_t)((nd * 16 + lrow) * (VLD * 2)) + cByte;
                ldmatrix_x4(t, uVh + ro);
                vbh[0][0] = t[0]; vbh[0][1] = t[2];
                vbh[1][0] = t[1]; vbh[1][1] = t[3];
                ldmatrix_x4(t, uVl + ro);
                vbl[0][0] = t[0]; vbl[0][1] = t[2];
                vbl[1][0] = t[1]; vbl[1][1] = t[3];
#pragma unroll
                for (int f = 0; f < 2; f++) {
                    float* d = oacc[nd * 2 + f];
                    mma_bf16(d, pah, vbh[f]);
                    mma_bf16(d, pah, vbl[f]);
                    mma_bf16(d, pal, vbh[f]);
                }
            }
        }
    }

    // ---- normalize + store fp32 ----
    const int g  = lane >> 2;
    const int t2 = (lane & 3) * 2;
    const float inv0 = 1.f / l0;
    const float inv1 = 1.f / l1;
    const int row0 = q0 + wid * 16 + g;
    float* ob = g_att + (tokbase + row0) * CH + h * HDIM;
#pragma unroll
    for (int j = 0; j < 8; j++) {
        *(float2*)(ob + j * 8 + t2) =
            make_float2(oacc[j][0] * inv0, oacc[j][1] * inv0);
        *(float2*)(ob + 8 * (size_t)CH + j * 8 + t2) =
            make_float2(oacc[j][2] * inv1, oacc[j][3] * inv1);
    }
}

// ---------------------------------------------------------------------------
extern "C" void kernel_launch(void* const* d_in, const int* in_sizes, int n_in,
                              void* d_out, int out_size)
{
    const float* x      = (const float*)d_in[0];
    const float* w_qkv  = (const float*)d_in[1];
    const float* w_proj = (const float*)d_in[2];
    const float* b_proj = (const float*)d_in[3];
    float* out = (float*)d_out;

    float* att;
    __nv_bfloat16 *qh, *ql, *wqh, *wql, *wph, *wpl;
    cudaGetSymbolAddress((void**)&att, g_att);
    cudaGetSymbolAddress((void**)&qh, g_qh);
    cudaGetSymbolAddress((void**)&ql, g_ql);
    cudaGetSymbolAddress((void**)&wqh, g_wqh);
    cudaGetSymbolAddress((void**)&wql, g_wql);
    cudaGetSymbolAddress((void**)&wph, g_wph);
    cudaGetSymbolAddress((void**)&wpl, g_wpl);

    // 0) Weight transpose + bf16 split
    transpose_split_kernel<<<dim3(QKV_LD / 32, CH / 32), dim3(32, 8)>>>(
        w_qkv, wqh, wql, CH, QKV_LD);
    transpose_split_kernel<<<dim3(CH / 32, CH / 32), dim3(32, 8)>>>(
        w_proj, wph, wpl, CH, CH);

    // 1) QKV projection -> split bf16 qkv (q pre-scaled)
    gemm_mma_kernel<<<dim3(QKV_LD / 128, (B_SZ * SEQ) / 128), 256>>>(
        x, wqh, wql, nullptr, nullptr, qh, ql,
        B_SZ * SEQ, QKV_LD, CH, 0, CH);

    // 2) Flash attention (bf16-split mma)
    cudaFuncSetAttribute(flash_mma_kernel,
                         cudaFuncAttributeMaxDynamicSharedMemorySize, FLASH_SMEM);
    flash_mma_kernel<<<dim3(SEQ / 128, B_SZ * NHEAD), 256, FLASH_SMEM>>>();

    // 3) Output projection + bias (fp32 epilogue)
    gemm_mma_kernel<<<dim3(CH / 128, (B_SZ * SEQ) / 128), 256>>>(
        att, wph, wpl, b_proj, out, nullptr, nullptr,
        B_SZ * SEQ, CH, CH, 1, 0);
}

// round 6
// speedup vs baseline: 2.0550x; 1.1610x over previous
#include <cuda_runtime.h>
#include <cuda_bf16.h>
#include <cstdint>

#define B_SZ   8
#define SEQ    1024
#define CH     768
#define NHEAD  12
#define HDIM   64
#define QKV_LD (3*CH)      /* 2304 */
#define ATT_SCALE 0.125f   /* 64^-0.5 */

// ---------------------------------------------------------------------------
// Scratch (device globals; runtime allocation is forbidden)
// ---------------------------------------------------------------------------
__device__ __nv_bfloat16 g_xh[(size_t)B_SZ * SEQ * CH];      // x hi
__device__ __nv_bfloat16 g_xl[(size_t)B_SZ * SEQ * CH];      // x lo
__device__ __nv_bfloat16 g_qh[(size_t)B_SZ * SEQ * QKV_LD];  // qkv hi (q pre-scaled)
__device__ __nv_bfloat16 g_ql[(size_t)B_SZ * SEQ * QKV_LD];  // qkv lo
__device__ __nv_bfloat16 g_ath[(size_t)B_SZ * SEQ * CH];     // attention out hi
__device__ __nv_bfloat16 g_atl[(size_t)B_SZ * SEQ * CH];     // attention out lo
__device__ __nv_bfloat16 g_wqh[(size_t)QKV_LD * CH];
__device__ __nv_bfloat16 g_wql[(size_t)QKV_LD * CH];
__device__ __nv_bfloat16 g_wph[(size_t)CH * CH];
__device__ __nv_bfloat16 g_wpl[(size_t)CH * CH];

// ---------------------------------------------------------------------------
__device__ __forceinline__ uint32_t smem_u32(const void* p) {
    uint32_t a;
    asm("{ .reg .u64 t; cvta.to.shared.u64 t, %1; cvt.u32.u64 %0, t; }"
        : "=r"(a) : "l"(p));
    return a;
}
__device__ __forceinline__ void ldmatrix_x4(uint32_t* r, uint32_t addr) {
    asm volatile("ldmatrix.sync.aligned.m8n8.x4.shared.b16 {%0,%1,%2,%3}, [%4];"
                 : "=r"(r[0]), "=r"(r[1]), "=r"(r[2]), "=r"(r[3]) : "r"(addr));
}
__device__ __forceinline__ void mma_bf16(float* d, const uint32_t* a,
                                         const uint32_t* b) {
    asm volatile(
        "mma.sync.aligned.m16n8k16.row.col.f32.bf16.bf16.f32 "
        "{%0,%1,%2,%3},{%4,%5,%6,%7},{%8,%9},{%0,%1,%2,%3};"
        : "+f"(d[0]), "+f"(d[1]), "+f"(d[2]), "+f"(d[3])
        : "r"(a[0]), "r"(a[1]), "r"(a[2]), "r"(a[3]), "r"(b[0]), "r"(b[1]));
}
__device__ __forceinline__ void cp16(uint32_t s, const void* g) {
    asm volatile("cp.async.cg.shared.global [%0], [%1], 16;"
                 :: "r"(s), "l"(g));
}
__device__ __forceinline__ void cp_commit() {
    asm volatile("cp.async.commit_group;" ::: "memory");
}
__device__ __forceinline__ void cp_wait0() {
    asm volatile("cp.async.wait_group 0;" ::: "memory");
}
__device__ __forceinline__ uint32_t pack_bf2(__nv_bfloat16 a, __nv_bfloat16 b) {
    return (uint32_t)__bfloat16_as_ushort(a) |
           ((uint32_t)__bfloat16_as_ushort(b) << 16);
}
__device__ __forceinline__ void split_pack(float x, float y,
                                           uint32_t& hi, uint32_t& lo) {
    const __nv_bfloat16 hx = __float2bfloat16(x);
    const __nv_bfloat16 hy = __float2bfloat16(y);
    hi = pack_bf2(hx, hy);
    lo = pack_bf2(__float2bfloat16(x - __bfloat162float(hx)),
                  __float2bfloat16(y - __bfloat162float(hy)));
}

// ---------------------------------------------------------------------------
// Elementwise fp32 -> bf16 hi/lo split (for x)
// ---------------------------------------------------------------------------
__global__ void split_kernel(const float* __restrict__ X,
                             __nv_bfloat16* __restrict__ Xh,
                             __nv_bfloat16* __restrict__ Xl)
{
    const size_t i = ((size_t)blockIdx.x * blockDim.x + threadIdx.x) * 4;
    const float4 v = *(const float4*)(X + i);
    uint32_t h0, l0, h1, l1;
    split_pack(v.x, v.y, h0, l0);
    split_pack(v.z, v.w, h1, l1);
    *(uint2*)(Xh + i) = make_uint2(h0, h1);
    *(uint2*)(Xl + i) = make_uint2(l0, l1);
}

// ---------------------------------------------------------------------------
// Weight prep: W[K,N] fp32 -> WT hi/lo [N,K] bf16
// ---------------------------------------------------------------------------
__global__ void transpose_split_kernel(const float* __restrict__ W,
                                       __nv_bfloat16* __restrict__ Th,
                                       __nv_bfloat16* __restrict__ Tl,
                                       int K, int Nn)
{
    __shared__ float tile[32][33];
    const int n0 = blockIdx.x * 32;
    const int k0 = blockIdx.y * 32;
    const int tx = threadIdx.x;
    for (int i = threadIdx.y; i < 32; i += 8)
        tile[i][tx] = W[(size_t)(k0 + i) * Nn + n0 + tx];
    __syncthreads();
    for (int i = threadIdx.y; i < 32; i += 8) {
        const float v = tile[tx][i];
        const __nv_bfloat16 h = __float2bfloat16(v);
        const __nv_bfloat16 l = __float2bfloat16(v - __bfloat162float(h));
        const size_t o = (size_t)(n0 + i) * K + k0 + tx;
        Th[o] = h;
        Tl[o] = l;
    }
}

// ---------------------------------------------------------------------------
// All-bf16 split GEMM via mma.sync + cp.async 2-stage pipeline.
// C[M,N] = (Ah+Al)[M,K] @ (Bh+Bl)[N,K]^T (3-term), epilogues:
//   Chi!=null : bf16 hi/lo split out (cols < qcols scaled by ATT_SCALE)
//   else      : fp32 + bias
// CTA tile 128x128, BK=32, 8 warps (4m x 2n).
// ---------------------------------------------------------------------------
#define LDA 40                       /* bf16 per smem row (32 data + 8 pad) */
#define ARR_BYTES (128 * LDA * 2)    /* 10240 */
#define STAGE_BYTES (4 * ARR_BYTES)  /* 40960 */
#define GEMM_SMEM (2 * STAGE_BYTES)  /* 81920 */

__global__ __launch_bounds__(256) void gemm_bf16_kernel(
    const __nv_bfloat16* __restrict__ Ah, const __nv_bfloat16* __restrict__ Al,
    const __nv_bfloat16* __restrict__ Bh, const __nv_bfloat16* __restrict__ Bl,
    const float* __restrict__ bias, float* __restrict__ C,
    __nv_bfloat16* __restrict__ Chi, __nv_bfloat16* __restrict__ Clo,
    int M, int Nn, int K, int has_bias, int qcols)
{
    extern __shared__ __align__(16) char dsm[];
    const uint32_t sbase = smem_u32(dsm);

    const int tid  = threadIdx.x;
    const int wid  = tid >> 5;
    const int lane = tid & 31;
    const int wr   = wid >> 1;
    const int wc   = wid & 1;
    const int bm   = blockIdx.y * 128;
    const int bn   = blockIdx.x * 128;

    // loader: row = tid>>1, 16-col half = (tid&1)*16 -> two 16B chunks/array
    const int r    = tid >> 1;
    const int half = tid & 1;
    const __nv_bfloat16* gp[4];
    gp[0] = Ah + (size_t)(bm + r) * K + half * 16;
    gp[1] = Al + (size_t)(bm + r) * K + half * 16;
    gp[2] = Bh + (size_t)(bn + r) * K + half * 16;
    gp[3] = Bl + (size_t)(bn + r) * K + half * 16;
    const uint32_t st_byte = (uint32_t)(r * LDA + half * 16) * 2;

    const int lrow = lane & 15;
    const int lcol = (lane >> 4) << 3;

    float acc[2][8][4];
#pragma unroll
    for (int a = 0; a < 2; a++)
#pragma unroll
        for (int b = 0; b < 8; b++)
#pragma unroll
            for (int j = 0; j < 4; j++) acc[a][b][j] = 0.f;

    const int NIT = K / 32;

    // prologue: stage 0
#pragma unroll
    for (int arr = 0; arr < 4; arr++) {
        const uint32_t sa = sbase + arr * ARR_BYTES + st_byte;
        cp16(sa, gp[arr]);
        cp16(sa + 16, gp[arr] + 8);
    }
    cp_commit();

    for (int it = 0; it < NIT; it++) {
        cp_wait0();
        __syncthreads();

        if (it + 1 < NIT) {
            const int k0 = (it + 1) * 32;
            const uint32_t us = sbase + ((it + 1) & 1) * STAGE_BYTES;
#pragma unroll
            for (int arr = 0; arr < 4; arr++) {
                const uint32_t sa = us + arr * ARR_BYTES + st_byte;
                cp16(sa, gp[arr] + k0);
                cp16(sa + 16, gp[arr] + k0 + 8);
            }
            cp_commit();
        }

        const uint32_t uS  = sbase + (it & 1) * STAGE_BYTES;
        const uint32_t uAh = uS;
        const uint32_t uAl = uS + ARR_BYTES;
        const uint32_t uBh = uS + 2 * ARR_BYTES;
        const uint32_t uBl = uS + 3 * ARR_BYTES;

#pragma unroll
        for (int kk = 0; kk < 2; kk++) {
            const uint32_t cByte = (uint32_t)((kk * 16 + lcol) * 2);
            uint32_t ah[2][4], al[2][4];
#pragma unroll
            for (int a = 0; a < 2; a++) {
                const uint32_t ro =
                    (uint32_t)((wr * 32 + a * 16 + lrow) * (LDA * 2)) + cByte;
                ldmatrix_x4(ah[a], uAh + ro);
                ldmatrix_x4(al[a], uAl + ro);
            }
            uint32_t bh[8][2], bl[8][2];
#pragma unroll
            for (int g = 0; g < 4; g++) {
                uint32_t t[4];
                const uint32_t ro =
                    (uint32_t)((wc * 64 + g * 16 + lrow) * (LDA * 2)) + cByte;
                ldmatrix_x4(t, uBh + ro);
                bh[g * 2][0] = t[0]; bh[g * 2][1] = t[2];
                bh[g * 2 + 1][0] = t[1]; bh[g * 2 + 1][1] = t[3];
                ldmatrix_x4(t, uBl + ro);
                bl[g * 2][0] = t[0]; bl[g * 2][1] = t[2];
                bl[g * 2 + 1][0] = t[1]; bl[g * 2 + 1][1] = t[3];
            }
#pragma unroll
            for (int a = 0; a < 2; a++)
#pragma unroll
                for (int b = 0; b < 8; b++) {
                    mma_bf16(acc[a][b], ah[a], bh[b]);
                    mma_bf16(acc[a][b], ah[a], bl[b]);
                    mma_bf16(acc[a][b], al[a], bh[b]);
                }
        }
        __syncthreads();
    }

    const int g  = lane >> 2;
    const int t2 = (lane & 3) * 2;
#pragma unroll
    for (int a = 0; a < 2; a++) {
        const int row0 = bm + wr * 32 + a * 16 + g;
#pragma unroll
        for (int b = 0; b < 8; b++) {
            const int col = bn + wc * 64 + b * 8 + t2;
            if (Chi) {
                const float sc = (col < qcols) ? ATT_SCALE : 1.f;
                uint32_t h0, l0, h1, l1;
                split_pack(acc[a][b][0] * sc, acc[a][b][1] * sc, h0, l0);
                split_pack(acc[a][b][2] * sc, acc[a][b][3] * sc, h1, l1);
                const size_t o0 = (size_t)row0 * Nn + col;
                const size_t o1 = (size_t)(row0 + 8) * Nn + col;
                *(uint32_t*)(Chi + o0) = h0;
                *(uint32_t*)(Clo + o0) = l0;
                *(uint32_t*)(Chi + o1) = h1;
                *(uint32_t*)(Clo + o1) = l1;
            } else {
                float bx = 0.f, by = 0.f;
                if (has_bias) { bx = bias[col]; by = bias[col + 1]; }
                *(float2*)(C + (size_t)row0 * Nn + col) =
                    make_float2(acc[a][b][0] + bx, acc[a][b][1] + by);
                *(float2*)(C + (size_t)(row0 + 8) * Nn + col) =
                    make_float2(acc[a][b][2] + bx, acc[a][b][3] + by);
            }
        }
    }
}

// ---------------------------------------------------------------------------
// Flash attention via bf16-split mma.sync (epilogue writes split bf16).
// Grid (SEQ/128, B*H), 256 threads (8 warps x 16 q-rows).
// ---------------------------------------------------------------------------
#define KLD 72    /* bf16 per K/Q smem row (64 data + 8 pad)   */
#define VLD 136   /* bf16 per Vt smem row (128 data + 8 pad)   */
#define OKH 0
#define OKL (128 * KLD)
#define OVH (2 * 128 * KLD)
#define OVL (2 * 128 * KLD + 64 * VLD)
#define FLASH_SMEM ((2 * 128 * KLD + 2 * 64 * VLD) * 2)

__global__ __launch_bounds__(256, 1) void flash_mma_kernel()
{
    extern __shared__ __align__(16) __nv_bfloat16 sm[];
    __nv_bfloat16* Kh = sm + OKH;
    __nv_bfloat16* Kl = sm + OKL;
    __nv_bfloat16* Vh = sm + OVH;
    __nv_bfloat16* Vl = sm + OVL;

    const int tid  = threadIdx.x;
    const int wid  = tid >> 5;
    const int lane = tid & 31;
    const int lrow = lane & 15;
    const int lcol = (lane >> 4) << 3;
    const int q0 = blockIdx.x * 128;
    const int b  = blockIdx.y / NHEAD;
    const int h  = blockIdx.y % NHEAD;

    const size_t tokbase = (size_t)b * SEQ;
    const __nv_bfloat16* qh_g = g_qh + tokbase * QKV_LD + h * HDIM;
    const __nv_bfloat16* ql_g = g_ql + tokbase * QKV_LD + h * HDIM;
    const __nv_bfloat16* kh_g = qh_g + CH;
    const __nv_bfloat16* kl_g = ql_g + CH;
    const __nv_bfloat16* vh_g = qh_g + 2 * CH;
    const __nv_bfloat16* vl_g = ql_g + 2 * CH;

    const uint32_t uKh = smem_u32(Kh), uKl = smem_u32(Kl);
    const uint32_t uVh = smem_u32(Vh), uVl = smem_u32(Vl);

    const int ldr  = tid >> 1;
    const int ldh  = (tid & 1) * 32;

    // ---- stage Q into K buffers (32 bf16 = 4x uint4 per thread) ----
    {
        const __nv_bfloat16* sh = qh_g + (size_t)(q0 + ldr) * QKV_LD + ldh;
        const __nv_bfloat16* sl = ql_g + (size_t)(q0 + ldr) * QKV_LD + ldh;
#pragma unroll
        for (int i = 0; i < 4; i++) {
            *(uint4*)&Kh[ldr * KLD + ldh + i * 8] = *(const uint4*)(sh + i * 8);
            *(uint4*)&Kl[ldr * KLD + ldh + i * 8] = *(const uint4*)(sl + i * 8);
        }
    }
    __syncthreads();

    uint32_t qfh[4][4], qfl[4][4];
#pragma unroll
    for (int ks = 0; ks < 4; ks++) {
        const uint32_t ro =
            (uint32_t)((wid * 16 + lrow) * (KLD * 2)) + (ks * 16 + lcol) * 2;
        ldmatrix_x4(qfh[ks], uKh + ro);
        ldmatrix_x4(qfl[ks], uKl + ro);
    }

    float m0 = -1e30f, m1 = -1e30f, l0 = 0.f, l1 = 0.f;
    float oacc[8][4];
#pragma unroll
    for (int j = 0; j < 8; j++)
#pragma unroll
        for (int c = 0; c < 4; c++) oacc[j][c] = 0.f;

    for (int jt = 0; jt < SEQ; jt += 128) {
        __syncthreads();
        {
            const __nv_bfloat16* skh = kh_g + (size_t)(jt + ldr) * QKV_LD + ldh;
            const __nv_bfloat16* skl = kl_g + (size_t)(jt + ldr) * QKV_LD + ldh;
#pragma unroll
            for (int i = 0; i < 4; i++) {
                *(uint4*)&Kh[ldr * KLD + ldh + i * 8] = *(const uint4*)(skh + i * 8);
                *(uint4*)&Kl[ldr * KLD + ldh + i * 8] = *(const uint4*)(skl + i * 8);
            }
            const __nv_bfloat16* svh = vh_g + (size_t)(jt + ldr) * QKV_LD + ldh;
            const __nv_bfloat16* svl = vl_g + (size_t)(jt + ldr) * QKV_LD + ldh;
            uint4 th[4], tl[4];
#pragma unroll
            for (int i = 0; i < 4; i++) {
                th[i] = *(const uint4*)(svh + i * 8);
                tl[i] = *(const uint4*)(svl + i * 8);
            }
            const ushort* ph = (const ushort*)th;
            const ushort* pl = (const ushort*)tl;
#pragma unroll
            for (int i = 0; i < 32; i++) {
                ((ushort*)Vh)[(ldh + i) * VLD + ldr] = ph[i];
                ((ushort*)Vl)[(ldh + i) * VLD + ldr] = pl[i];
            }
        }
        __syncthreads();

        // ---- S = Q @ K^T (3-term) ----
        float sacc[16][4];
#pragma unroll
        for (int j = 0; j < 16; j++)
#pragma unroll
            for (int c = 0; c < 4; c++) sacc[j][c] = 0.f;

#pragma unroll
        for (int ks = 0; ks < 4; ks++) {
            const uint32_t cByte = (uint32_t)((ks * 16 + lcol) * 2);
#pragma unroll
            for (int ng = 0; ng < 4; ng++) {
                uint32_t bh[4][2], bl[4][2], t[4];
#pragma unroll
                for (int h2 = 0; h2 < 2; h2++) {
                    const uint32_t ro =
                        (uint32_t)((ng * 32 + h2 * 16 + lrow) * (KLD * 2)) + cByte;
                    ldmatrix_x4(t, uKh + ro);
                    bh[h2 * 2][0] = t[0]; bh[h2 * 2][1] = t[2];
                    bh[h2 * 2 + 1][0] = t[1]; bh[h2 * 2 + 1][1] = t[3];
                    ldmatrix_x4(t, uKl + ro);
                    bl[h2 * 2][0] = t[0]; bl[h2 * 2][1] = t[2];
                    bl[h2 * 2 + 1][0] = t[1]; bl[h2 * 2 + 1][1] = t[3];
                }
#pragma unroll
                for (int f = 0; f < 4; f++) {
                    float* d = sacc[ng * 4 + f];
                    mma_bf16(d, qfh[ks], bh[f]);
                    mma_bf16(d, qfh[ks], bl[f]);
                    mma_bf16(d, qfl[ks], bh[f]);
                }
            }
        }

        // ---- online softmax ----
        float mx0 = sacc[0][0], mx1 = sacc[0][2];
#pragma unroll
        for (int j = 0; j < 16; j++) {
            mx0 = fmaxf(mx0, fmaxf(sacc[j][0], sacc[j][1]));
            mx1 = fmaxf(mx1, fmaxf(sacc[j][2], sacc[j][3]));
        }
        mx0 = fmaxf(mx0, __shfl_xor_sync(0xffffffffu, mx0, 1));
        mx0 = fmaxf(mx0, __shfl_xor_sync(0xffffffffu, mx0, 2));
        mx1 = fmaxf(mx1, __shfl_xor_sync(0xffffffffu, mx1, 1));
        mx1 = fmaxf(mx1, __shfl_xor_sync(0xffffffffu, mx1, 2));

        const float mn0 = fmaxf(m0, mx0);
        const float mn1 = fmaxf(m1, mx1);
        const float cr0 = __expf(m0 - mn0);
        const float cr1 = __expf(m1 - mn1);
        m0 = mn0; m1 = mn1;

        float ps0 = 0.f, ps1 = 0.f;
#pragma unroll
        for (int j = 0; j < 16; j++) {
            sacc[j][0] = __expf(sacc[j][0] - mn0);
            sacc[j][1] = __expf(sacc[j][1] - mn0);
            sacc[j][2] = __expf(sacc[j][2] - mn1);
            sacc[j][3] = __expf(sacc[j][3] - mn1);
            ps0 += sacc[j][0] + sacc[j][1];
            ps1 += sacc[j][2] + sacc[j][3];
        }
        ps0 += __shfl_xor_sync(0xffffffffu, ps0, 1);
        ps0 += __shfl_xor_sync(0xffffffffu, ps0, 2);
        ps1 += __shfl_xor_sync(0xffffffffu, ps1, 1);
        ps1 += __shfl_xor_sync(0xffffffffu, ps1, 2);
        l0 = l0 * cr0 + ps0;
        l1 = l1 * cr1 + ps1;

#pragma unroll
        for (int j = 0; j < 8; j++) {
            oacc[j][0] *= cr0; oacc[j][1] *= cr0;
            oacc[j][2] *= cr1; oacc[j][3] *= cr1;
        }

        // ---- O += P @ V (3-term; P packed in-register) ----
#pragma unroll
        for (int ks = 0; ks < 8; ks++) {
            uint32_t pah[4], pal[4];
            split_pack(sacc[2 * ks][0], sacc[2 * ks][1], pah[0], pal[0]);
            split_pack(sacc[2 * ks][2], sacc[2 * ks][3], pah[1], pal[1]);
            split_pack(sacc[2 * ks + 1][0], sacc[2 * ks + 1][1], pah[2], pal[2]);
            split_pack(sacc[2 * ks + 1][2], sacc[2 * ks + 1][3], pah[3], pal[3]);

            const uint32_t cByte = (uint32_t)((ks * 16 + lcol) * 2);
#pragma unroll
            for (int nd = 0; nd < 4; nd++) {
                uint32_t vbh[2][2], vbl[2][2], t[4];
                const uint32_t ro =
                    (uint32_t)((nd * 16 + lrow) * (VLD * 2)) + cByte;
                ldmatrix_x4(t, uVh + ro);
                vbh[0][0] = t[0]; vbh[0][1] = t[2];
                vbh[1][0] = t[1]; vbh[1][1] = t[3];
                ldmatrix_x4(t, uVl + ro);
                vbl[0][0] = t[0]; vbl[0][1] = t[2];
                vbl[1][0] = t[1]; vbl[1][1] = t[3];
#pragma unroll
                for (int f = 0; f < 2; f++) {
                    float* d = oacc[nd * 2 + f];
                    mma_bf16(d, pah, vbh[f]);
                    mma_bf16(d, pah, vbl[f]);
                    mma_bf16(d, pal, vbh[f]);
                }
            }
        }
    }

    // ---- normalize + store split bf16 ----
    const int g  = lane >> 2;
    const int t2 = (lane & 3) * 2;
    const float inv0 = 1.f / l0;
    const float inv1 = 1.f / l1;
    const int row0 = q0 + wid * 16 + g;
    __nv_bfloat16* oh = g_ath + (tokbase + row0) * CH + h * HDIM;
    __nv_bfloat16* ol = g_atl + (tokbase + row0) * CH + h * HDIM;
#pragma unroll
    for (int j = 0; j < 8; j++) {
        uint32_t hh, ll;
        split_pack(oacc[j][0] * inv0, oacc[j][1] * inv0, hh, ll);
        *(uint32_t*)(oh + j * 8 + t2) = hh;
        *(uint32_t*)(ol + j * 8 + t2) = ll;
        split_pack(oacc[j][2] * inv1, oacc[j][3] * inv1, hh, ll);
        *(uint32_t*)(oh + 8 * (size_t)CH + j * 8 + t2) = hh;
        *(uint32_t*)(ol + 8 * (size_t)CH + j * 8 + t2) = ll;
    }
}

// ---------------------------------------------------------------------------
extern "C" void kernel_launch(void* const* d_in, const int* in_sizes, int n_in,
                              void* d_out, int out_size)
{
    const float* x      = (const float*)d_in[0];
    const float* w_qkv  = (const float*)d_in[1];
    const float* w_proj = (const float*)d_in[2];
    const float* b_proj = (const float*)d_in[3];
    float* out = (float*)d_out;

    __nv_bfloat16 *xh, *xl, *qh, *ql, *ath, *atl, *wqh, *wql, *wph, *wpl;
    cudaGetSymbolAddress((void**)&xh, g_xh);
    cudaGetSymbolAddress((void**)&xl, g_xl);
    cudaGetSymbolAddress((void**)&qh, g_qh);
    cudaGetSymbolAddress((void**)&ql, g_ql);
    cudaGetSymbolAddress((void**)&ath, g_ath);
    cudaGetSymbolAddress((void**)&atl, g_atl);
    cudaGetSymbolAddress((void**)&wqh, g_wqh);
    cudaGetSymbolAddress((void**)&wql, g_wql);
    cudaGetSymbolAddress((void**)&wph, g_wph);
    cudaGetSymbolAddress((void**)&wpl, g_wpl);

    // 0) prep: x split + weight transpose/split
    split_kernel<<<(B_SZ * SEQ * CH) / (256 * 4), 256>>>(x, xh, xl);
    transpose_split_kernel<<<dim3(QKV_LD / 32, CH / 32), dim3(32, 8)>>>(
        w_qkv, wqh, wql, CH, QKV_LD);
    transpose_split_kernel<<<dim3(CH / 32, CH / 32), dim3(32, 8)>>>(
        w_proj, wph, wpl, CH, CH);

    // 1) QKV projection -> split bf16 qkv (q pre-scaled)
    cudaFuncSetAttribute(gemm_bf16_kernel,
                         cudaFuncAttributeMaxDynamicSharedMemorySize, GEMM_SMEM);
    gemm_bf16_kernel<<<dim3(QKV_LD / 128, (B_SZ * SEQ) / 128), 256, GEMM_SMEM>>>(
        xh, xl, wqh, wql, nullptr, nullptr, qh, ql,
        B_SZ * SEQ, QKV_LD, CH, 0, CH);

    // 2) Flash attention (bf16-split mma) -> split bf16 att
    cudaFuncSetAttribute(flash_mma_kernel,
                         cudaFuncAttributeMaxDynamicSharedMemorySize, FLASH_SMEM);
    flash_mma_kernel<<<dim3(SEQ / 128, B_SZ * NHEAD), 256, FLASH_SMEM>>>();

    // 3) Output projection + bias (fp32 epilogue)
    gemm_bf16_kernel<<<dim3(CH / 128, (B_SZ * SEQ) / 128), 256, GEMM_SMEM>>>(
        ath, atl, wph, wpl, b_proj, out, nullptr, nullptr,
        B_SZ * SEQ, CH, CH, 1, 0);
}

// round 7
// speedup vs baseline: 2.3127x; 1.1254x over previous
#include <cuda_runtime.h>
#include <cuda_bf16.h>
#include <cstdint>

#define B_SZ   8
#define SEQ    1024
#define CH     768
#define NHEAD  12
#define HDIM   64
#define QKV_LD (3*CH)
#define ATT_SCALE 0.125f

__device__ __nv_bfloat16 g_xh[(size_t)B_SZ * SEQ * CH];
__device__ __nv_bfloat16 g_xl[(size_t)B_SZ * SEQ * CH];
__device__ __nv_bfloat16 g_qh[(size_t)B_SZ * SEQ * QKV_LD];
__device__ __nv_bfloat16 g_ql[(size_t)B_SZ * SEQ * QKV_LD];
__device__ __nv_bfloat16 g_ath[(size_t)B_SZ * SEQ * CH];
__device__ __nv_bfloat16 g_atl[(size_t)B_SZ * SEQ * CH];
__device__ __nv_bfloat16 g_wqh[(size_t)QKV_LD * CH];
__device__ __nv_bfloat16 g_wql[(size_t)QKV_LD * CH];
__device__ __nv_bfloat16 g_wph[(size_t)CH * CH];
__device__ __nv_bfloat16 g_wpl[(size_t)CH * CH];

__device__ __forceinline__ uint32_t smem_u32(const void* p) {
    uint32_t a;
    asm("{ .reg .u64 t; cvta.to.shared.u64 t, %1; cvt.u32.u64 %0, t; }"
        : "=r"(a) : "l"(p));
    return a;
}
__device__ __forceinline__ void ldmatrix_x4(uint32_t* r, uint32_t addr) {
    asm volatile("ldmatrix.sync.aligned.m8n8.x4.shared.b16 {%0,%1,%2,%3}, [%4];"
                 : "=r"(r[0]), "=r"(r[1]), "=r"(r[2]), "=r"(r[3]) : "r"(addr));
}
__device__ __forceinline__ void ldmatrix_x4_trans(uint32_t* r, uint32_t addr) {
    asm volatile("ldmatrix.sync.aligned.m8n8.x4.trans.shared.b16 {%0,%1,%2,%3}, [%4];"
                 : "=r"(r[0]), "=r"(r[1]), "=r"(r[2]), "=r"(r[3]) : "r"(addr));
}
__device__ __forceinline__ void mma_bf16(float* d, const uint32_t* a,
                                         const uint32_t* b) {
    asm volatile(
        "mma.sync.aligned.m16n8k16.row.col.f32.bf16.bf16.f32 "
        "{%0,%1,%2,%3},{%4,%5,%6,%7},{%8,%9},{%0,%1,%2,%3};"
        : "+f"(d[0]), "+f"(d[1]), "+f"(d[2]), "+f"(d[3])
        : "r"(a[0]), "r"(a[1]), "r"(a[2]), "r"(a[3]), "r"(b[0]), "r"(b[1]));
}
__device__ __forceinline__ void cp16(uint32_t s, const void* g) {
    asm volatile("cp.async.cg.shared.global [%0], [%1], 16;" :: "r"(s), "l"(g));
}
__device__ __forceinline__ void cp_commit() {
    asm volatile("cp.async.commit_group;" ::: "memory");
}
__device__ __forceinline__ void cp_wait0() {
    asm volatile("cp.async.wait_group 0;" ::: "memory");
}
__device__ __forceinline__ uint32_t pack_bf2(__nv_bfloat16 a, __nv_bfloat16 b) {
    return (uint32_t)__bfloat16_as_ushort(a) |
           ((uint32_t)__bfloat16_as_ushort(b) << 16);
}
__device__ __forceinline__ void split_pack(float x, float y,
                                           uint32_t& hi, uint32_t& lo) {
    const __nv_bfloat16 hx = __float2bfloat16(x);
    const __nv_bfloat16 hy = __float2bfloat16(y);
    hi = pack_bf2(hx, hy);
    lo = pack_bf2(__float2bfloat16(x - __bfloat162float(hx)),
                  __float2bfloat16(y - __bfloat162float(hy)));
}

__global__ void split_kernel(const float* __restrict__ X,
                             __nv_bfloat16* __restrict__ Xh,
                             __nv_bfloat16* __restrict__ Xl)
{
    const size_t i = ((size_t)blockIdx.x * blockDim.x + threadIdx.x) * 4;
    const float4 v = *(const float4*)(X + i);
    uint32_t h0, l0, h1, l1;
    split_pack(v.x, v.y, h0, l0);
    split_pack(v.z, v.w, h1, l1);
    *(uint2*)(Xh + i) = make_uint2(h0, h1);
    *(uint2*)(Xl + i) = make_uint2(l0, l1);
}

__global__ void transpose_split_kernel(const float* __restrict__ W,
                                       __nv_bfloat16* __restrict__ Th,
                                       __nv_bfloat16* __restrict__ Tl,
                                       int K, int Nn)
{
    __shared__ float tile[32][33];
    const int n0 = blockIdx.x * 32;
    const int k0 = blockIdx.y * 32;
    const int tx = threadIdx.x;
    for (int i = threadIdx.y; i < 32; i += 8)
        tile[i][tx] = W[(size_t)(k0 + i) * Nn + n0 + tx];
    __syncthreads();
    for (int i = threadIdx.y; i < 32; i += 8) {
        const float v = tile[tx][i];
        const __nv_bfloat16 h = __float2bfloat16(v);
        const __nv_bfloat16 l = __float2bfloat16(v - __bfloat162float(h));
        const size_t o = (size_t)(n0 + i) * K + k0 + tx;
        Th[o] = h;
        Tl[o] = l;
    }
}

// ---------------------------------------------------------------------------
// All-bf16 split GEMM (unchanged from Round 6)
// ---------------------------------------------------------------------------
#define LDA 40
#define ARR_BYTES (128 * LDA * 2)
#define STAGE_BYTES (4 * ARR_BYTES)
#define GEMM_SMEM (2 * STAGE_BYTES)

__global__ __launch_bounds__(256) void gemm_bf16_kernel(
    const __nv_bfloat16* __restrict__ Ah, const __nv_bfloat16* __restrict__ Al,
    const __nv_bfloat16* __restrict__ Bh, const __nv_bfloat16* __restrict__ Bl,
    const float* __restrict__ bias, float* __restrict__ C,
    __nv_bfloat16* __restrict__ Chi, __nv_bfloat16* __restrict__ Clo,
    int M, int Nn, int K, int has_bias, int qcols)
{
    extern __shared__ __align__(16) char dsm[];
    const uint32_t sbase = smem_u32(dsm);

    const int tid  = threadIdx.x;
    const int wid  = tid >> 5;
    const int lane = tid & 31;
    const int wr   = wid >> 1;
    const int wc   = wid & 1;
    const int bm   = blockIdx.y * 128;
    const int bn   = blockIdx.x * 128;

    const int r    = tid >> 1;
    const int half = tid & 1;
    const __nv_bfloat16* gp[4];
    gp[0] = Ah + (size_t)(bm + r) * K + half * 16;
    gp[1] = Al + (size_t)(bm + r) * K + half * 16;
    gp[2] = Bh + (size_t)(bn + r) * K + half * 16;
    gp[3] = Bl + (size_t)(bn + r) * K + half * 16;
    const uint32_t st_byte = (uint32_t)(r * LDA + half * 16) * 2;

    const int lrow = lane & 15;
    const int lcol = (lane >> 4) << 3;

    float acc[2][8][4];
#pragma unroll
    for (int a = 0; a < 2; a++)
#pragma unroll
        for (int b = 0; b < 8; b++)
#pragma unroll
            for (int j = 0; j < 4; j++) acc[a][b][j] = 0.f;

    const int NIT = K / 32;

#pragma unroll
    for (int arr = 0; arr < 4; arr++) {
        const uint32_t sa = sbase + arr * ARR_BYTES + st_byte;
        cp16(sa, gp[arr]);
        cp16(sa + 16, gp[arr] + 8);
    }
    cp_commit();

    for (int it = 0; it < NIT; it++) {
        cp_wait0();
        __syncthreads();

        if (it + 1 < NIT) {
            const int k0 = (it + 1) * 32;
            const uint32_t us = sbase + ((it + 1) & 1) * STAGE_BYTES;
#pragma unroll
            for (int arr = 0; arr < 4; arr++) {
                const uint32_t sa = us + arr * ARR_BYTES + st_byte;
                cp16(sa, gp[arr] + k0);
                cp16(sa + 16, gp[arr] + k0 + 8);
            }
            cp_commit();
        }

        const uint32_t uS  = sbase + (it & 1) * STAGE_BYTES;
        const uint32_t uAh = uS;
        const uint32_t uAl = uS + ARR_BYTES;
        const uint32_t uBh = uS + 2 * ARR_BYTES;
        const uint32_t uBl = uS + 3 * ARR_BYTES;

#pragma unroll
        for (int kk = 0; kk < 2; kk++) {
            const uint32_t cByte = (uint32_t)((kk * 16 + lcol) * 2);
            uint32_t ah[2][4], al[2][4];
#pragma unroll
            for (int a = 0; a < 2; a++) {
                const uint32_t ro =
                    (uint32_t)((wr * 32 + a * 16 + lrow) * (LDA * 2)) + cByte;
                ldmatrix_x4(ah[a], uAh + ro);
                ldmatrix_x4(al[a], uAl + ro);
            }
            uint32_t bh[8][2], bl[8][2];
#pragma unroll
            for (int g = 0; g < 4; g++) {
                uint32_t t[4];
                const uint32_t ro =
                    (uint32_t)((wc * 64 + g * 16 + lrow) * (LDA * 2)) + cByte;
                ldmatrix_x4(t, uBh + ro);
                bh[g * 2][0] = t[0]; bh[g * 2][1] = t[2];
                bh[g * 2 + 1][0] = t[1]; bh[g * 2 + 1][1] = t[3];
                ldmatrix_x4(t, uBl + ro);
                bl[g * 2][0] = t[0]; bl[g * 2][1] = t[2];
                bl[g * 2 + 1][0] = t[1]; bl[g * 2 + 1][1] = t[3];
            }
#pragma unroll
            for (int a = 0; a < 2; a++)
#pragma unroll
                for (int b = 0; b < 8; b++) {
                    mma_bf16(acc[a][b], ah[a], bh[b]);
                    mma_bf16(acc[a][b], ah[a], bl[b]);
                    mma_bf16(acc[a][b], al[a], bh[b]);
                }
        }
        __syncthreads();
    }

    const int g  = lane >> 2;
    const int t2 = (lane & 3) * 2;
#pragma unroll
    for (int a = 0; a < 2; a++) {
        const int row0 = bm + wr * 32 + a * 16 + g;
#pragma unroll
        for (int b = 0; b < 8; b++) {
            const int col = bn + wc * 64 + b * 8 + t2;
            if (Chi) {
                const float sc = (col < qcols) ? ATT_SCALE : 1.f;
                uint32_t h0, l0, h1, l1;
                split_pack(acc[a][b][0] * sc, acc[a][b][1] * sc, h0, l0);
                split_pack(acc[a][b][2] * sc, acc[a][b][3] * sc, h1, l1);
                const size_t o0 = (size_t)row0 * Nn + col;
                const size_t o1 = (size_t)(row0 + 8) * Nn + col;
                *(uint32_t*)(Chi + o0) = h0;
                *(uint32_t*)(Clo + o0) = l0;
                *(uint32_t*)(Chi + o1) = h1;
                *(uint32_t*)(Clo + o1) = l1;
            } else {
                float bx = 0.f, by = 0.f;
                if (has_bias) { bx = bias[col]; by = bias[col + 1]; }
                *(float2*)(C + (size_t)row0 * Nn + col) =
                    make_float2(acc[a][b][0] + bx, acc[a][b][1] + by);
                *(float2*)(C + (size_t)(row0 + 8) * Nn + col) =
                    make_float2(acc[a][b][2] + bx, acc[a][b][3] + by);
            }
        }
    }
}

// ---------------------------------------------------------------------------
// Flash attention: V via ldmatrix.trans (no scatter), cp.async double-buffered
// K/V staging, one barrier per KV tile. Grid (SEQ/128, B*H), 256 threads.
// ---------------------------------------------------------------------------
#define KLD 72
#define FARR_BYTES (128 * KLD * 2)
#define FSTG_BYTES (4 * FARR_BYTES)
#define FLASH_SMEM (2 * FSTG_BYTES)

__global__ __launch_bounds__(256, 1) void flash_mma_kernel()
{
    extern __shared__ __align__(16) char fsm[];
    const uint32_t sbase = smem_u32(fsm);

    const int tid  = threadIdx.x;
    const int wid  = tid >> 5;
    const int lane = tid & 31;
    const int lrow = lane & 15;
    const int lcol = (lane >> 4) << 3;
    const int q0 = blockIdx.x * 128;
    const int b  = blockIdx.y / NHEAD;
    const int h  = blockIdx.y % NHEAD;

    const size_t tokbase = (size_t)b * SEQ;
    const __nv_bfloat16* qh_g = g_qh + tokbase * QKV_LD + h * HDIM;
    const __nv_bfloat16* ql_g = g_ql + tokbase * QKV_LD + h * HDIM;
    const __nv_bfloat16* kh_g = qh_g + CH;
    const __nv_bfloat16* kl_g = ql_g + CH;
    const __nv_bfloat16* vh_g = qh_g + 2 * CH;
    const __nv_bfloat16* vl_g = ql_g + 2 * CH;

    // ---- stage Q into stage-1 K buffers (direct stores) ----
    {
        __nv_bfloat16* Kh1 = (__nv_bfloat16*)(fsm + FSTG_BYTES);
        __nv_bfloat16* Kl1 = (__nv_bfloat16*)(fsm + FSTG_BYTES + FARR_BYTES);
        const int ldr = tid >> 1;
        const int ldh = (tid & 1) * 32;
        const __nv_bfloat16* sh = qh_g + (size_t)(q0 + ldr) * QKV_LD + ldh;
        const __nv_bfloat16* sl = ql_g + (size_t)(q0 + ldr) * QKV_LD + ldh;
#pragma unroll
        for (int i = 0; i < 4; i++) {
            *(uint4*)&Kh1[ldr * KLD + ldh + i * 8] = *(const uint4*)(sh + i * 8);
            *(uint4*)&Kl1[ldr * KLD + ldh + i * 8] = *(const uint4*)(sl + i * 8);
        }
    }
    __syncthreads();

    // ---- prologue: issue tile-0 K/V loads into stage 0 ----
    {
        const __nv_bfloat16* gsrc[4] = { kh_g, kl_g, vh_g, vl_g };
#pragma unroll
        for (int arr = 0; arr < 4; arr++)
#pragma unroll
            for (int c = 0; c < 4; c++) {
                const int ch  = tid + c * 256;
                const int row = ch >> 3;
                const int col = ch & 7;
                cp16(sbase + arr * FARR_BYTES + (uint32_t)(row * KLD + col * 8) * 2,
                     gsrc[arr] + (size_t)row * QKV_LD + col * 8);
            }
        cp_commit();
    }

    // ---- Q fragments from stage-1 K buffers ----
    uint32_t qfh[4][4], qfl[4][4];
    {
        const uint32_t uQh = sbase + FSTG_BYTES;
        const uint32_t uQl = uQh + FARR_BYTES;
#pragma unroll
        for (int ks = 0; ks < 4; ks++) {
            const uint32_t ro =
                (uint32_t)((wid * 16 + lrow) * (KLD * 2)) + (ks * 16 + lcol) * 2;
            ldmatrix_x4(qfh[ks], uQh + ro);
            ldmatrix_x4(qfl[ks], uQl + ro);
        }
    }

    float m0 = -1e30f, m1 = -1e30f, l0 = 0.f, l1 = 0.f;
    float oacc[8][4];
#pragma unroll
    for (int j = 0; j < 8; j++)
#pragma unroll
        for (int c = 0; c < 4; c++) oacc[j][c] = 0.f;

    for (int t = 0; t < SEQ / 128; t++) {
        const int s = t & 1;
        cp_wait0();
        __syncthreads();

        if (t + 1 < SEQ / 128) {
            const int jn = (t + 1) * 128;
            const uint32_t us = sbase + (s ^ 1) * FSTG_BYTES;
            const __nv_bfloat16* gsrc[4] = { kh_g, kl_g, vh_g, vl_g };
#pragma unroll
            for (int arr = 0; arr < 4; arr++)
#pragma unroll
                for (int c = 0; c < 4; c++) {
                    const int ch  = tid + c * 256;
                    const int row = ch >> 3;
                    const int col = ch & 7;
                    cp16(us + arr * FARR_BYTES + (uint32_t)(row * KLD + col * 8) * 2,
                         gsrc[arr] + (size_t)(jn + row) * QKV_LD + col * 8);
                }
            cp_commit();
        }

        const uint32_t uS  = sbase + s * FSTG_BYTES;
        const uint32_t uKh = uS;
        const uint32_t uKl = uS + FARR_BYTES;
        const uint32_t uVh = uS + 2 * FARR_BYTES;
        const uint32_t uVl = uS + 3 * FARR_BYTES;

        // ---- S = Q @ K^T (3-term) ----
        float sacc[16][4];
#pragma unroll
        for (int j = 0; j < 16; j++)
#pragma unroll
            for (int c = 0; c < 4; c++) sacc[j][c] = 0.f;

#pragma unroll
        for (int ks = 0; ks < 4; ks++) {
            const uint32_t cByte = (uint32_t)((ks * 16 + lcol) * 2);
#pragma unroll
            for (int ng = 0; ng < 4; ng++) {
                uint32_t bh[4][2], bl[4][2], tt[4];
#pragma unroll
                for (int h2 = 0; h2 < 2; h2++) {
                    const uint32_t ro =
                        (uint32_t)((ng * 32 + h2 * 16 + lrow) * (KLD * 2)) + cByte;
                    ldmatrix_x4(tt, uKh + ro);
                    bh[h2 * 2][0] = tt[0]; bh[h2 * 2][1] = tt[2];
                    bh[h2 * 2 + 1][0] = tt[1]; bh[h2 * 2 + 1][1] = tt[3];
                    ldmatrix_x4(tt, uKl + ro);
                    bl[h2 * 2][0] = tt[0]; bl[h2 * 2][1] = tt[2];
                    bl[h2 * 2 + 1][0] = tt[1]; bl[h2 * 2 + 1][1] = tt[3];
                }
#pragma unroll
                for (int f = 0; f < 4; f++) {
                    float* d = sacc[ng * 4 + f];
                    mma_bf16(d, qfh[ks], bh[f]);
                    mma_bf16(d, qfh[ks], bl[f]);
                    mma_bf16(d, qfl[ks], bh[f]);
                }
            }
        }

        // ---- online softmax ----
        float mx0 = sacc[0][0], mx1 = sacc[0][2];
#pragma unroll
        for (int j = 0; j < 16; j++) {
            mx0 = fmaxf(mx0, fmaxf(sacc[j][0], sacc[j][1]));
            mx1 = fmaxf(mx1, fmaxf(sacc[j][2], sacc[j][3]));
        }
        mx0 = fmaxf(mx0, __shfl_xor_sync(0xffffffffu, mx0, 1));
        mx0 = fmaxf(mx0, __shfl_xor_sync(0xffffffffu, mx0, 2));
        mx1 = fmaxf(mx1, __shfl_xor_sync(0xffffffffu, mx1, 1));
        mx1 = fmaxf(mx1, __shfl_xor_sync(0xffffffffu, mx1, 2));

        const float mn0 = fmaxf(m0, mx0);
        const float mn1 = fmaxf(m1, mx1);
        const float cr0 = __expf(m0 - mn0);
        const float cr1 = __expf(m1 - mn1);
        m0 = mn0; m1 = mn1;

        float ps0 = 0.f, ps1 = 0.f;
#pragma unroll
        for (int j = 0; j < 16; j++) {
            sacc[j][0] = __expf(sacc[j][0] - mn0);
            sacc[j][1] = __expf(sacc[j][1] - mn0);
            sacc[j][2] = __expf(sacc[j][2] - mn1);
            sacc[j][3] = __expf(sacc[j][3] - mn1);
            ps0 += sacc[j][0] + sacc[j][1];
            ps1 += sacc[j][2] + sacc[j][3];
        }
        ps0 += __shfl_xor_sync(0xffffffffu, ps0, 1);
        ps0 += __shfl_xor_sync(0xffffffffu, ps0, 2);
        ps1 += __shfl_xor_sync(0xffffffffu, ps1, 1);
        ps1 += __shfl_xor_sync(0xffffffffu, ps1, 2);
        l0 = l0 * cr0 + ps0;
        l1 = l1 * cr1 + ps1;

#pragma unroll
        for (int j = 0; j < 8; j++) {
            oacc[j][0] *= cr0; oacc[j][1] *= cr0;
            oacc[j][2] *= cr1; oacc[j][3] *= cr1;
        }

        // ---- O += P @ V (3-term; V B-fragments via ldmatrix.trans) ----
#pragma unroll
        for (int ks = 0; ks < 8; ks++) {
            uint32_t pah[4], pal[4];
            split_pack(sacc[2 * ks][0], sacc[2 * ks][1], pah[0], pal[0]);
            split_pack(sacc[2 * ks][2], sacc[2 * ks][3], pah[1], pal[1]);
            split_pack(sacc[2 * ks + 1][0], sacc[2 * ks + 1][1], pah[2], pal[2]);
            split_pack(sacc[2 * ks + 1][2], sacc[2 * ks + 1][3], pah[3], pal[3]);

#pragma unroll
            for (int nd = 0; nd < 4; nd++) {
                // V rows = keys ks*16+lrow, byte col = d (nd*16 + lcol)
                // trans x4: t[0]=b0(d+0..7) t[1]=b1(d+0..7) t[2]=b0(d+8..15) t[3]=b1(d+8..15)
                const uint32_t ro =
                    (uint32_t)((ks * 16 + lrow) * (KLD * 2)) +
                    (uint32_t)((nd * 16 + lcol) * 2);
                uint32_t th[4], tl[4];
                ldmatrix_x4_trans(th, uVh + ro);
                ldmatrix_x4_trans(tl, uVl + ro);
#pragma unroll
                for (int f = 0; f < 2; f++) {
                    float* d = oacc[nd * 2 + f];
                    uint32_t vh2[2] = { th[f * 2], th[f * 2 + 1] };
                    uint32_t vl2[2] = { tl[f * 2], tl[f * 2 + 1] };
                    mma_bf16(d, pah, vh2);
                    mma_bf16(d, pah, vl2);
                    mma_bf16(d, pal, vh2);
                }
            }
        }
    }

    // ---- normalize + store split bf16 ----
    const int g  = lane >> 2;
    const int t2 = (lane & 3) * 2;
    const float inv0 = 1.f / l0;
    const float inv1 = 1.f / l1;
    const int row0 = q0 + wid * 16 + g;
    __nv_bfloat16* oh = g_ath + (tokbase + row0) * CH + h * HDIM;
    __nv_bfloat16* ol = g_atl + (tokbase + row0) * CH + h * HDIM;
#pragma unroll
    for (int j = 0; j < 8; j++) {
        uint32_t hh, ll;
        split_pack(oacc[j][0] * inv0, oacc[j][1] * inv0, hh, ll);
        *(uint32_t*)(oh + j * 8 + t2) = hh;
        *(uint32_t*)(ol + j * 8 + t2) = ll;
        split_pack(oacc[j][2] * inv1, oacc[j][3] * inv1, hh, ll);
        *(uint32_t*)(oh + 8 * (size_t)CH + j * 8 + t2) = hh;
        *(uint32_t*)(ol + 8 * (size_t)CH + j * 8 + t2) = ll;
    }
}

// ---------------------------------------------------------------------------
extern "C" void kernel_launch(void* const* d_in, const int* in_sizes, int n_in,
                              void* d_out, int out_size)
{
    const float* x      = (const float*)d_in[0];
    const float* w_qkv  = (const float*)d_in[1];
    const float* w_proj = (const float*)d_in[2];
    const float* b_proj = (const float*)d_in[3];
    float* out = (float*)d_out;

    __nv_bfloat16 *xh, *xl, *qh, *ql, *ath, *atl, *wqh, *wql, *wph, *wpl;
    cudaGetSymbolAddress((void**)&xh, g_xh);
    cudaGetSymbolAddress((void**)&xl, g_xl);
    cudaGetSymbolAddress((void**)&qh, g_qh);
    cudaGetSymbolAddress((void**)&ql, g_ql);
    cudaGetSymbolAddress((void**)&ath, g_ath);
    cudaGetSymbolAddress((void**)&atl, g_atl);
    cudaGetSymbolAddress((void**)&wqh, g_wqh);
    cudaGetSymbolAddress((void**)&wql, g_wql);
    cudaGetSymbolAddress((void**)&wph, g_wph);
    cudaGetSymbolAddress((void**)&wpl, g_wpl);

    split_kernel<<<(B_SZ * SEQ * CH) / (256 * 4), 256>>>(x, xh, xl);
    transpose_split_kernel<<<dim3(QKV_LD / 32, CH / 32), dim3(32, 8)>>>(
        w_qkv, wqh, wql, CH, QKV_LD);
    transpose_split_kernel<<<dim3(CH / 32, CH / 32), dim3(32, 8)>>>(
        w_proj, wph, wpl, CH, CH);

    cudaFuncSetAttribute(gemm_bf16_kernel,
                         cudaFuncAttributeMaxDynamicSharedMemorySize, GEMM_SMEM);
    gemm_bf16_kernel<<<dim3(QKV_LD / 128, (B_SZ * SEQ) / 128), 256, GEMM_SMEM>>>(
        xh, xl, wqh, wql, nullptr, nullptr, qh, ql,
        B_SZ * SEQ, QKV_LD, CH, 0, CH);

    cudaFuncSetAttribute(flash_mma_kernel,
                         cudaFuncAttributeMaxDynamicSharedMemorySize, FLASH_SMEM);
    flash_mma_kernel<<<dim3(SEQ / 128, B_SZ * NHEAD), 256, FLASH_SMEM>>>();

    gemm_bf16_kernel<<<dim3(CH / 128, (B_SZ * SEQ) / 128), 256, GEMM_SMEM>>>(
        ath, atl, wph, wpl, b_proj, out, nullptr, nullptr,
        B_SZ * SEQ, CH, CH, 1, 0);
}